// round 3
// baseline (speedup 1.0000x reference)
#include <cuda_runtime.h>
#include <cuda_bf16.h>
#include <math.h>

#define N_NODES 50000
#define N_EDGES 640000
#define F 128
#define NG 256
#define NC 10
#define NL 3

// ---------------- device scratch (no allocations allowed) ----------------
__device__ float g_X[N_NODES * F];     // current node features
__device__ float g_H[N_NODES * F];     // post-GEMM features
__device__ float g_att[N_NODES];
__device__ float g_dinv[N_NODES];
__device__ int   g_indeg[N_NODES];
__device__ int   g_rowptr[N_NODES + 1];
__device__ int   g_fill[N_NODES];
__device__ int   g_col[N_EDGES];
__device__ float g_stats[2 * F];       // [0:128) sum, [128:256) sumsq
__device__ int   g_gcount[NG];
__device__ float g_rep[NG * 3 * F];    // graph representation accumulator
__device__ int   g_is64;               // 1 if index buffers are int64

// ---------------- helpers ----------------
__device__ __forceinline__ float warp_sum(float v) {
    #pragma unroll
    for (int o = 16; o; o >>= 1) v += __shfl_xor_sync(0xffffffffu, v, o);
    return v;
}

__device__ __forceinline__ int load_idx(const void* p, long long i, int is64) {
    if (is64) return (int)((const long long*)p)[i];
    return ((const int*)p)[i];
}

// ---------------- dtype detection ----------------
// If indices are int32 but misread as int64, each 8-byte word packs two
// indices (lo + hi*2^32) -> value >= 2^32 whenever hi != 0, far outside
// [0, N_NODES). Check samples from both rows of edge_index.
__global__ void detect_kernel(const void* ei) {
    if (threadIdx.x == 0) {
        const long long* p = (const long long*)ei;
        int ok64 = 1;
        for (int i = 0; i < 32; i++) {
            long long a = p[i];
            long long b = p[N_EDGES + i];   // dst row under int64 interpretation
            if (a < 0 || a >= N_NODES || b < 0 || b >= N_NODES) { ok64 = 0; break; }
        }
        g_is64 = ok64;
    }
}

// ---------------- zero scratch ----------------
__global__ void zero_kernel() {
    int i = blockIdx.x * blockDim.x + threadIdx.x;
    int stride = gridDim.x * blockDim.x;
    for (int j = i; j < NG * 3 * F; j += stride) g_rep[j] = 0.0f;
    for (int j = i; j < N_NODES; j += stride) { g_indeg[j] = 0; g_fill[j] = 0; }
    for (int j = i; j < 2 * F; j += stride) g_stats[j] = 0.0f;
    for (int j = i; j < NG; j += stride) g_gcount[j] = 0;
}

// ---------------- batchnorm stats ----------------
__global__ void bn_stats_kernel(const float* __restrict__ x) {
    int f = threadIdx.x;
    int r0 = blockIdx.x * 512;
    int r1 = min(r0 + 512, N_NODES);
    float s = 0.0f, s2 = 0.0f;
    for (int r = r0; r < r1; r++) {
        float v = x[r * F + f];
        s += v; s2 += v * v;
    }
    atomicAdd(&g_stats[f], s);
    atomicAdd(&g_stats[F + f], s2);
}

__global__ void bn_apply_kernel(const float* __restrict__ x,
                                const float* __restrict__ gamma,
                                const float* __restrict__ beta) {
    int i = blockIdx.x * blockDim.x + threadIdx.x;          // float4 index
    int total4 = N_NODES * F / 4;
    if (i >= total4) return;
    int f4 = i & (F / 4 - 1);
    const float4* x4 = (const float4*)x;
    float4 v = x4[i];
    float inv_n = 1.0f / (float)N_NODES;
    #pragma unroll
    for (int j = 0; j < 4; j++) {
        int f = f4 * 4 + j;
        float mu = g_stats[f] * inv_n;
        float var = g_stats[F + f] * inv_n - mu * mu;
        float rstd = rsqrtf(var + 1e-5f);
        float xv = (&v.x)[j];
        (&v.x)[j] = (xv - mu) * rstd * gamma[f] + beta[f];
    }
    ((float4*)g_X)[i] = v;
}

// ---------------- graph structure ----------------
__global__ void deg_count_kernel(const void* __restrict__ ei) {
    int e = blockIdx.x * blockDim.x + threadIdx.x;
    if (e >= N_EDGES) return;
    int is64 = g_is64;
    int s = load_idx(ei, e, is64);
    int d = load_idx(ei, (long long)N_EDGES + e, is64);
    if (s != d) atomicAdd(&g_indeg[d], 1);
}

__global__ void gcount_kernel(const void* __restrict__ batch) {
    int n = blockIdx.x * blockDim.x + threadIdx.x;
    if (n >= N_NODES) return;
    atomicAdd(&g_gcount[load_idx(batch, n, g_is64)], 1);
}

// single-block exclusive scan of g_indeg -> g_rowptr, plus dinv
__global__ void scan_kernel() {
    __shared__ int tot[1024];
    const int T = 1024;
    const int CH = (N_NODES + T - 1) / T;
    int t = threadIdx.x;
    int b = t * CH;
    int e = min(b + CH, N_NODES);
    int s = 0;
    for (int i = b; i < e; i++) s += g_indeg[i];
    tot[t] = s;
    __syncthreads();
    for (int off = 1; off < T; off <<= 1) {
        int v = (t >= off) ? tot[t - off] : 0;
        __syncthreads();
        tot[t] += v;
        __syncthreads();
    }
    int run = tot[t] - s;   // exclusive base for this chunk
    for (int i = b; i < e; i++) {
        g_rowptr[i] = run;
        run += g_indeg[i];
        g_dinv[i] = rsqrtf((float)(g_indeg[i] + 1));
    }
    if (t == 0) g_rowptr[N_NODES] = tot[T - 1];
}

__global__ void scatter_kernel(const void* __restrict__ ei) {
    int e = blockIdx.x * blockDim.x + threadIdx.x;
    if (e >= N_EDGES) return;
    int is64 = g_is64;
    int s = load_idx(ei, e, is64);
    int d = load_idx(ei, (long long)N_EDGES + e, is64);
    if (s != d) {
        int pos = g_rowptr[d] + atomicAdd(&g_fill[d], 1);
        g_col[pos] = s;
    }
}

// ---------------- GEMM: g_H = g_X @ W  (M=50000, N=128, K=128) ----------------
// 64x64 tile, BK=64 (2 k-steps), 256 threads, 4x4 register tile
__global__ __launch_bounds__(256) void gemm_kernel(const float* __restrict__ W) {
    const int m0 = blockIdx.y * 64;
    const int n0 = blockIdx.x * 64;
    __shared__ float As[64 * 68];
    __shared__ float Bs[64 * 68];
    int tid = threadIdx.x;
    int tx = tid & 15, ty = tid >> 4;

    float acc[4][4];
    #pragma unroll
    for (int i = 0; i < 4; i++)
        #pragma unroll
        for (int j = 0; j < 4; j++) acc[i][j] = 0.0f;

    for (int k0 = 0; k0 < 128; k0 += 64) {
        // A tile: 64 rows x 64 cols = 1024 float4
        for (int i = tid; i < 1024; i += 256) {
            int r = i >> 4, c4 = i & 15;
            int gr = m0 + r;
            float4 v = (gr < N_NODES) ? ((const float4*)g_X)[gr * 32 + (k0 >> 2) + c4]
                                      : make_float4(0.f, 0.f, 0.f, 0.f);
            As[r * 68 + c4 * 4 + 0] = v.x;
            As[r * 68 + c4 * 4 + 1] = v.y;
            As[r * 68 + c4 * 4 + 2] = v.z;
            As[r * 68 + c4 * 4 + 3] = v.w;
        }
        // B tile: rows k0..k0+63, cols n0..n0+63
        for (int i = tid; i < 1024; i += 256) {
            int r = i >> 4, c4 = i & 15;
            float4 v = ((const float4*)W)[(k0 + r) * 32 + (n0 >> 2) + c4];
            Bs[r * 68 + c4 * 4 + 0] = v.x;
            Bs[r * 68 + c4 * 4 + 1] = v.y;
            Bs[r * 68 + c4 * 4 + 2] = v.z;
            Bs[r * 68 + c4 * 4 + 3] = v.w;
        }
        __syncthreads();

        #pragma unroll 8
        for (int k = 0; k < 64; k++) {
            float a[4], b[4];
            #pragma unroll
            for (int i = 0; i < 4; i++) a[i] = As[(ty * 4 + i) * 68 + k];
            #pragma unroll
            for (int j = 0; j < 4; j++) b[j] = Bs[k * 68 + tx * 4 + j];
            #pragma unroll
            for (int i = 0; i < 4; i++)
                #pragma unroll
                for (int j = 0; j < 4; j++) acc[i][j] = fmaf(a[i], b[j], acc[i][j]);
        }
        __syncthreads();
    }

    #pragma unroll
    for (int i = 0; i < 4; i++) {
        int gr = m0 + ty * 4 + i;
        if (gr < N_NODES) {
            float4 v = make_float4(acc[i][0], acc[i][1], acc[i][2], acc[i][3]);
            ((float4*)g_H)[gr * 32 + ((n0 + tx * 4) >> 2)] = v;
        }
    }
}

// ---------------- aggregate + bias + squash + attention ----------------
// one warp per node; lane l owns features [4l, 4l+4)
__global__ __launch_bounds__(256) void agg_squash_kernel(const float* __restrict__ bias,
                                                         const float* __restrict__ watt) {
    int gtid = blockIdx.x * blockDim.x + threadIdx.x;
    int n = gtid >> 5;
    if (n >= N_NODES) return;
    int l = threadIdx.x & 31;

    const float4* H4 = (const float4*)g_H;
    float di = g_dinv[n];
    float4 hv = H4[n * 32 + l];
    float w = di * di;                      // self loop weight
    float4 acc = make_float4(w * hv.x, w * hv.y, w * hv.z, w * hv.w);

    int beg = g_rowptr[n], end = g_rowptr[n + 1];
    for (int e = beg; e < end; e++) {
        int s = g_col[e];
        float we = di * g_dinv[s];
        float4 v = H4[s * 32 + l];
        acc.x = fmaf(we, v.x, acc.x);
        acc.y = fmaf(we, v.y, acc.y);
        acc.z = fmaf(we, v.z, acc.z);
        acc.w = fmaf(we, v.w, acc.w);
    }
    float4 b4 = ((const float4*)bias)[l];
    acc.x += b4.x; acc.y += b4.y; acc.z += b4.z; acc.w += b4.w;

    float n2p = acc.x * acc.x + acc.y * acc.y + acc.z * acc.z + acc.w * acc.w;
    float n2 = warp_sum(n2p);
    float scl = (n2 / (1.0f + n2)) * rsqrtf(n2 + 1e-8f);
    float4 out = make_float4(scl * acc.x, scl * acc.y, scl * acc.z, scl * acc.w);
    ((float4*)g_X)[n * 32 + l] = out;

    float4 w4 = ((const float4*)watt)[l];
    float ap = out.x * w4.x + out.y * w4.y + out.z * w4.z + out.w * w4.w;
    float a = warp_sum(ap);
    if (l == 0) g_att[n] = a;
}

// ---------------- per-graph readout (batch is sorted) ----------------
__global__ void readout_kernel(const void* __restrict__ batch) {
    int g = blockIdx.x;
    int f = threadIdx.x;
    int is64 = g_is64;

    int lo = 0, hi = N_NODES;
    while (lo < hi) { int mid = (lo + hi) >> 1; if (load_idx(batch, mid, is64) < g) lo = mid + 1; else hi = mid; }
    int start = lo;
    lo = start; hi = N_NODES;
    while (lo < hi) { int mid = (lo + hi) >> 1; if (load_idx(batch, mid, is64) < g + 1) lo = mid + 1; else hi = mid; }
    int end = lo;

    float ws = 0.0f, sm = 0.0f, mx = -INFINITY;
    for (int n = start; n < end; n++) {
        float v = g_X[n * F + f];
        float a = g_att[n];
        ws = fmaf(a, v, ws);
        sm += v;
        mx = fmaxf(mx, v);
    }
    float cnt = fmaxf((float)g_gcount[g], 1.0f);
    g_rep[g * 3 * F + f]         += ws;
    g_rep[g * 3 * F + F + f]     += sm / cnt;
    g_rep[g * 3 * F + 2 * F + f] += (start < end) ? mx : 0.0f;
}

// ---------------- final MLP + log_softmax ----------------
__global__ void mlp_kernel(const float* __restrict__ W1, const float* __restrict__ b1,
                           const float* __restrict__ W2, const float* __restrict__ b2,
                           float* __restrict__ out) {
    __shared__ float h[F];
    __shared__ float lg[NC];
    int g = blockIdx.x;
    int j = threadIdx.x;

    float acc = b1[j];
    const float* rep = &g_rep[g * 3 * F];
    for (int k = 0; k < 3 * F; k++)
        acc = fmaf(rep[k], W1[k * F + j], acc);
    h[j] = fmaxf(acc, 0.0f);
    __syncthreads();

    if (j < NC) {
        float l = b2[j];
        for (int k = 0; k < F; k++) l = fmaf(h[k], W2[k * NC + j], l);
        lg[j] = l;
    }
    __syncthreads();
    if (j < NC) {
        float m = -INFINITY;
        #pragma unroll
        for (int c = 0; c < NC; c++) m = fmaxf(m, lg[c]);
        float s = 0.0f;
        #pragma unroll
        for (int c = 0; c < NC; c++) s += expf(lg[c] - m);
        out[g * NC + j] = lg[j] - m - logf(s);
    }
}

// ---------------- launcher ----------------
extern "C" void kernel_launch(void* const* d_in, const int* in_sizes, int n_in,
                              void* d_out, int out_size) {
    const float* x      = (const float*)d_in[0];
    const void*  ei     = d_in[1];
    const void*  batch  = d_in[2];
    const float* gamma  = (const float*)d_in[3];
    const float* beta   = (const float*)d_in[4];
    const float* gcn_w  = (const float*)d_in[5];
    const float* gcn_b  = (const float*)d_in[6];
    const float* w_att  = (const float*)d_in[7];
    const float* lin1_w = (const float*)d_in[8];
    const float* lin1_b = (const float*)d_in[9];
    const float* lin2_w = (const float*)d_in[10];
    const float* lin2_b = (const float*)d_in[11];
    float* out = (float*)d_out;

    detect_kernel<<<1, 32>>>(ei);
    zero_kernel<<<256, 256>>>();

    bn_stats_kernel<<<(N_NODES + 511) / 512, 128>>>(x);
    bn_apply_kernel<<<(N_NODES * F / 4 + 255) / 256, 256>>>(x, gamma, beta);

    deg_count_kernel<<<(N_EDGES + 255) / 256, 256>>>(ei);
    gcount_kernel<<<(N_NODES + 255) / 256, 256>>>(batch);
    scan_kernel<<<1, 1024>>>();
    scatter_kernel<<<(N_EDGES + 255) / 256, 256>>>(ei);

    dim3 gemm_grid(2, (N_NODES + 63) / 64);
    int agg_blocks = (N_NODES * 32 + 255) / 256;

    for (int i = 0; i < NL; i++) {
        gemm_kernel<<<gemm_grid, 256>>>(gcn_w + i * F * F);
        agg_squash_kernel<<<agg_blocks, 256>>>(gcn_b + i * F, w_att + i * F);
        readout_kernel<<<NG, F>>>(batch);
    }

    mlp_kernel<<<NG, F>>>(lin1_w, lin1_b, lin2_w, lin2_b, out);
}

// round 4
// speedup vs baseline: 1.2524x; 1.2524x over previous
#include <cuda_runtime.h>
#include <cuda_bf16.h>
#include <math.h>

#define N_NODES 50000
#define N_EDGES 640000
#define F 128
#define NG 256
#define NC 10
#define NL 3

// ---------------- device scratch (no allocations allowed) ----------------
__device__ float g_X[N_NODES * F];     // current node features
__device__ float g_H[N_NODES * F];     // post-GEMM features
__device__ float g_att[N_NODES];
__device__ float g_dinv[N_NODES];
__device__ int   g_indeg[N_NODES];
__device__ int   g_rowptr[N_NODES + 1];
__device__ int   g_fill[N_NODES];
__device__ int   g_col[N_EDGES];
__device__ float g_stats[2 * F];       // [0:128) sum, [128:256) sumsq
__device__ float g_bn_scale[F];
__device__ float g_bn_shift[F];
__device__ int   g_gcount[NG];
__device__ float g_rep[NG * 3 * F];    // graph representation accumulator
__device__ int   g_is64;               // 1 if index buffers are int64

// ---------------- helpers ----------------
__device__ __forceinline__ float warp_sum(float v) {
    #pragma unroll
    for (int o = 16; o; o >>= 1) v += __shfl_xor_sync(0xffffffffu, v, o);
    return v;
}

__device__ __forceinline__ int load_idx(const void* p, long long i, int is64) {
    if (is64) return (int)((const long long*)p)[i];
    return ((const int*)p)[i];
}

// ---------------- dtype detection ----------------
__global__ void detect_kernel(const void* ei) {
    if (threadIdx.x == 0) {
        const long long* p = (const long long*)ei;
        int ok64 = 1;
        for (int i = 0; i < 32; i++) {
            long long a = p[i];
            long long b = p[N_EDGES + i];
            if (a < 0 || a >= N_NODES || b < 0 || b >= N_NODES) { ok64 = 0; break; }
        }
        g_is64 = ok64;
    }
}

// ---------------- zero scratch ----------------
__global__ void zero_kernel() {
    int i = blockIdx.x * blockDim.x + threadIdx.x;
    int stride = gridDim.x * blockDim.x;
    for (int j = i; j < NG * 3 * F; j += stride) g_rep[j] = 0.0f;
    for (int j = i; j < N_NODES; j += stride) { g_indeg[j] = 0; g_fill[j] = 0; }
    for (int j = i; j < 2 * F; j += stride) g_stats[j] = 0.0f;
    for (int j = i; j < NG; j += stride) g_gcount[j] = 0;
}

// ---------------- batchnorm ----------------
// stats: each block = 128 threads (one per feature), 64 rows
__global__ void bn_stats_kernel(const float* __restrict__ x) {
    int f = threadIdx.x;
    int r0 = blockIdx.x * 64;
    int r1 = min(r0 + 64, N_NODES);
    float s = 0.0f, s2 = 0.0f;
    for (int r = r0; r < r1; r++) {
        float v = x[r * F + f];
        s += v; s2 = fmaf(v, v, s2);
    }
    atomicAdd(&g_stats[f], s);
    atomicAdd(&g_stats[F + f], s2);
}

__global__ void bn_prep_kernel(const float* __restrict__ gamma,
                               const float* __restrict__ beta) {
    int f = threadIdx.x;
    float inv_n = 1.0f / (float)N_NODES;
    float mu = g_stats[f] * inv_n;
    float var = g_stats[F + f] * inv_n - mu * mu;
    float rstd = rsqrtf(var + 1e-5f);
    float s = gamma[f] * rstd;
    g_bn_scale[f] = s;
    g_bn_shift[f] = beta[f] - mu * s;
}

// pure streaming apply: y = x*scl + sh
__global__ void bn_apply_kernel(const float* __restrict__ x) {
    int i = blockIdx.x * blockDim.x + threadIdx.x;     // float4 index
    int total4 = N_NODES * (F / 4);
    if (i >= total4) return;
    int f4 = i & (F / 4 - 1);
    float4 scl = ((const float4*)g_bn_scale)[f4];
    float4 sh  = ((const float4*)g_bn_shift)[f4];
    float4 v = ((const float4*)x)[i];
    v.x = fmaf(v.x, scl.x, sh.x);
    v.y = fmaf(v.y, scl.y, sh.y);
    v.z = fmaf(v.z, scl.z, sh.z);
    v.w = fmaf(v.w, scl.w, sh.w);
    ((float4*)g_X)[i] = v;
}

// ---------------- graph structure ----------------
__global__ void deg_count_kernel(const void* __restrict__ ei) {
    int e = blockIdx.x * blockDim.x + threadIdx.x;
    if (e >= N_EDGES) return;
    int is64 = g_is64;
    int s = load_idx(ei, e, is64);
    int d = load_idx(ei, (long long)N_EDGES + e, is64);
    if (s != d) atomicAdd(&g_indeg[d], 1);
}

__global__ void gcount_kernel(const void* __restrict__ batch) {
    int n = blockIdx.x * blockDim.x + threadIdx.x;
    if (n >= N_NODES) return;
    atomicAdd(&g_gcount[load_idx(batch, n, g_is64)], 1);
}

__global__ void scan_kernel() {
    __shared__ int tot[1024];
    const int T = 1024;
    const int CH = (N_NODES + T - 1) / T;
    int t = threadIdx.x;
    int b = t * CH;
    int e = min(b + CH, N_NODES);
    int s = 0;
    for (int i = b; i < e; i++) s += g_indeg[i];
    tot[t] = s;
    __syncthreads();
    for (int off = 1; off < T; off <<= 1) {
        int v = (t >= off) ? tot[t - off] : 0;
        __syncthreads();
        tot[t] += v;
        __syncthreads();
    }
    int run = tot[t] - s;
    for (int i = b; i < e; i++) {
        g_rowptr[i] = run;
        run += g_indeg[i];
        g_dinv[i] = rsqrtf((float)(g_indeg[i] + 1));
    }
    if (t == 0) g_rowptr[N_NODES] = tot[T - 1];
}

__global__ void scatter_kernel(const void* __restrict__ ei) {
    int e = blockIdx.x * blockDim.x + threadIdx.x;
    if (e >= N_EDGES) return;
    int is64 = g_is64;
    int s = load_idx(ei, e, is64);
    int d = load_idx(ei, (long long)N_EDGES + e, is64);
    if (s != d) {
        int pos = g_rowptr[d] + atomicAdd(&g_fill[d], 1);
        g_col[pos] = s;
    }
}

// ---------------- GEMM: g_H = g_X @ W  (M=50000, N=128, K=128) ----------------
// 128x128 tile (N covered fully), BK=32, 256 threads, 8x8 register tile,
// k-major smem so fragment loads are lds.128.
__global__ __launch_bounds__(256) void gemm_kernel(const float* __restrict__ W) {
    const int m0 = blockIdx.x * 128;
    __shared__ __align__(16) float As[32 * 132];   // [k][m], row stride 132
    __shared__ __align__(16) float Bs[32 * 128];   // [k][n]
    int tid = threadIdx.x;
    int tx = tid & 15, ty = tid >> 4;

    float acc[8][8];
    #pragma unroll
    for (int i = 0; i < 8; i++)
        #pragma unroll
        for (int j = 0; j < 8; j++) acc[i][j] = 0.0f;

    for (int k0 = 0; k0 < 128; k0 += 32) {
        // A tile: 128 rows x 32 cols, transposed into k-major
        #pragma unroll
        for (int t = 0; t < 4; t++) {
            int i = tid + t * 256;
            int r = i >> 3, c4 = i & 7;
            int gr = m0 + r;
            float4 v = (gr < N_NODES) ? ((const float4*)g_X)[gr * 32 + (k0 >> 2) + c4]
                                      : make_float4(0.f, 0.f, 0.f, 0.f);
            int kl = c4 * 4;
            As[(kl + 0) * 132 + r] = v.x;
            As[(kl + 1) * 132 + r] = v.y;
            As[(kl + 2) * 132 + r] = v.z;
            As[(kl + 3) * 132 + r] = v.w;
        }
        // B tile: 32 rows x 128 cols, direct copy
        #pragma unroll
        for (int t = 0; t < 4; t++) {
            int i = tid + t * 256;
            int r = i >> 5, c4 = i & 31;
            ((float4*)Bs)[r * 32 + c4] = ((const float4*)W)[(k0 + r) * 32 + c4];
        }
        __syncthreads();

        #pragma unroll 8
        for (int k = 0; k < 32; k++) {
            float a[8], b[8];
            *(float4*)&a[0] = *(const float4*)&As[k * 132 + ty * 8];
            *(float4*)&a[4] = *(const float4*)&As[k * 132 + ty * 8 + 4];
            *(float4*)&b[0] = *(const float4*)&Bs[k * 128 + tx * 8];
            *(float4*)&b[4] = *(const float4*)&Bs[k * 128 + tx * 8 + 4];
            #pragma unroll
            for (int i = 0; i < 8; i++)
                #pragma unroll
                for (int j = 0; j < 8; j++)
                    acc[i][j] = fmaf(a[i], b[j], acc[i][j]);
        }
        __syncthreads();
    }

    #pragma unroll
    for (int i = 0; i < 8; i++) {
        int gr = m0 + ty * 8 + i;
        if (gr < N_NODES) {
            ((float4*)g_H)[gr * 32 + tx * 2]     = make_float4(acc[i][0], acc[i][1], acc[i][2], acc[i][3]);
            ((float4*)g_H)[gr * 32 + tx * 2 + 1] = make_float4(acc[i][4], acc[i][5], acc[i][6], acc[i][7]);
        }
    }
}

// ---------------- aggregate + bias + squash + attention ----------------
__global__ __launch_bounds__(256) void agg_squash_kernel(const float* __restrict__ bias,
                                                         const float* __restrict__ watt) {
    int gtid = blockIdx.x * blockDim.x + threadIdx.x;
    int n = gtid >> 5;
    if (n >= N_NODES) return;
    int l = threadIdx.x & 31;

    const float4* __restrict__ H4 = (const float4*)g_H;
    float di = g_dinv[n];
    float4 hv = H4[n * 32 + l];
    float w = di * di;                      // self loop weight
    float4 acc = make_float4(w * hv.x, w * hv.y, w * hv.z, w * hv.w);

    int beg = g_rowptr[n], end = g_rowptr[n + 1];
    int e = beg;
    for (; e + 1 < end; e += 2) {
        int s0 = g_col[e], s1 = g_col[e + 1];
        float w0 = di * g_dinv[s0];
        float w1 = di * g_dinv[s1];
        float4 v0 = H4[s0 * 32 + l];
        float4 v1 = H4[s1 * 32 + l];
        acc.x = fmaf(w0, v0.x, acc.x); acc.x = fmaf(w1, v1.x, acc.x);
        acc.y = fmaf(w0, v0.y, acc.y); acc.y = fmaf(w1, v1.y, acc.y);
        acc.z = fmaf(w0, v0.z, acc.z); acc.z = fmaf(w1, v1.z, acc.z);
        acc.w = fmaf(w0, v0.w, acc.w); acc.w = fmaf(w1, v1.w, acc.w);
    }
    if (e < end) {
        int s0 = g_col[e];
        float w0 = di * g_dinv[s0];
        float4 v0 = H4[s0 * 32 + l];
        acc.x = fmaf(w0, v0.x, acc.x);
        acc.y = fmaf(w0, v0.y, acc.y);
        acc.z = fmaf(w0, v0.z, acc.z);
        acc.w = fmaf(w0, v0.w, acc.w);
    }
    float4 b4 = ((const float4*)bias)[l];
    acc.x += b4.x; acc.y += b4.y; acc.z += b4.z; acc.w += b4.w;

    float n2p = acc.x * acc.x + acc.y * acc.y + acc.z * acc.z + acc.w * acc.w;
    float n2 = warp_sum(n2p);
    float scl = (n2 / (1.0f + n2)) * rsqrtf(n2 + 1e-8f);
    float4 out = make_float4(scl * acc.x, scl * acc.y, scl * acc.z, scl * acc.w);
    ((float4*)g_X)[n * 32 + l] = out;

    float4 w4 = ((const float4*)watt)[l];
    float ap = out.x * w4.x + out.y * w4.y + out.z * w4.z + out.w * w4.w;
    float a = warp_sum(ap);
    if (l == 0) g_att[n] = a;
}

// ---------------- per-graph readout (batch is sorted) ----------------
__global__ void readout_kernel(const void* __restrict__ batch) {
    int g = blockIdx.x;
    int f = threadIdx.x;
    int is64 = g_is64;

    int lo = 0, hi = N_NODES;
    while (lo < hi) { int mid = (lo + hi) >> 1; if (load_idx(batch, mid, is64) < g) lo = mid + 1; else hi = mid; }
    int start = lo;
    lo = start; hi = N_NODES;
    while (lo < hi) { int mid = (lo + hi) >> 1; if (load_idx(batch, mid, is64) < g + 1) lo = mid + 1; else hi = mid; }
    int end = lo;

    float ws = 0.0f, sm = 0.0f, mx = -INFINITY;
    for (int n = start; n < end; n++) {
        float v = g_X[n * F + f];
        float a = g_att[n];
        ws = fmaf(a, v, ws);
        sm += v;
        mx = fmaxf(mx, v);
    }
    float cnt = fmaxf((float)g_gcount[g], 1.0f);
    g_rep[g * 3 * F + f]         += ws;
    g_rep[g * 3 * F + F + f]     += sm / cnt;
    g_rep[g * 3 * F + 2 * F + f] += (start < end) ? mx : 0.0f;
}

// ---------------- final MLP + log_softmax ----------------
__global__ void mlp_kernel(const float* __restrict__ W1, const float* __restrict__ b1,
                           const float* __restrict__ W2, const float* __restrict__ b2,
                           float* __restrict__ out) {
    __shared__ float h[F];
    __shared__ float lg[NC];
    int g = blockIdx.x;
    int j = threadIdx.x;

    float acc = b1[j];
    const float* rep = &g_rep[g * 3 * F];
    for (int k = 0; k < 3 * F; k++)
        acc = fmaf(rep[k], W1[k * F + j], acc);
    h[j] = fmaxf(acc, 0.0f);
    __syncthreads();

    if (j < NC) {
        float l = b2[j];
        for (int k = 0; k < F; k++) l = fmaf(h[k], W2[k * NC + j], l);
        lg[j] = l;
    }
    __syncthreads();
    if (j < NC) {
        float m = -INFINITY;
        #pragma unroll
        for (int c = 0; c < NC; c++) m = fmaxf(m, lg[c]);
        float s = 0.0f;
        #pragma unroll
        for (int c = 0; c < NC; c++) s += expf(lg[c] - m);
        out[g * NC + j] = lg[j] - m - logf(s);
    }
}

// ---------------- launcher ----------------
extern "C" void kernel_launch(void* const* d_in, const int* in_sizes, int n_in,
                              void* d_out, int out_size) {
    const float* x      = (const float*)d_in[0];
    const void*  ei     = d_in[1];
    const void*  batch  = d_in[2];
    const float* gamma  = (const float*)d_in[3];
    const float* beta   = (const float*)d_in[4];
    const float* gcn_w  = (const float*)d_in[5];
    const float* gcn_b  = (const float*)d_in[6];
    const float* w_att  = (const float*)d_in[7];
    const float* lin1_w = (const float*)d_in[8];
    const float* lin1_b = (const float*)d_in[9];
    const float* lin2_w = (const float*)d_in[10];
    const float* lin2_b = (const float*)d_in[11];
    float* out = (float*)d_out;

    // side stream + events created once, outside graph capture (first call is
    // the plain correctness run per harness contract)
    static cudaStream_t s1 = nullptr;
    static cudaEvent_t evFork, evStruct, evA0, evR0, evA1, evR1;
    if (!s1) {
        cudaStreamCreateWithFlags(&s1, cudaStreamNonBlocking);
        cudaEventCreateWithFlags(&evFork,   cudaEventDisableTiming);
        cudaEventCreateWithFlags(&evStruct, cudaEventDisableTiming);
        cudaEventCreateWithFlags(&evA0,     cudaEventDisableTiming);
        cudaEventCreateWithFlags(&evR0,     cudaEventDisableTiming);
        cudaEventCreateWithFlags(&evA1,     cudaEventDisableTiming);
        cudaEventCreateWithFlags(&evR1,     cudaEventDisableTiming);
    }
    cudaStream_t s0 = 0;

    detect_kernel<<<1, 32, 0, s0>>>(ei);
    zero_kernel<<<256, 256, 0, s0>>>();

    // fork structure build onto s1 (independent of BN/GEMM chain)
    cudaEventRecord(evFork, s0);
    cudaStreamWaitEvent(s1, evFork, 0);
    deg_count_kernel<<<(N_EDGES + 255) / 256, 256, 0, s1>>>(ei);
    gcount_kernel<<<(N_NODES + 255) / 256, 256, 0, s1>>>(batch);
    scan_kernel<<<1, 1024, 0, s1>>>();
    scatter_kernel<<<(N_EDGES + 255) / 256, 256, 0, s1>>>(ei);
    cudaEventRecord(evStruct, s1);

    // BN chain on s0
    bn_stats_kernel<<<(N_NODES + 63) / 64, 128, 0, s0>>>(x);
    bn_prep_kernel<<<1, F, 0, s0>>>(gamma, beta);
    bn_apply_kernel<<<(N_NODES * (F / 4) + 255) / 256, 256, 0, s0>>>(x);

    int gemm_grid = (N_NODES + 127) / 128;
    int agg_blocks = (N_NODES * 32 + 255) / 256;

    // layer 0
    gemm_kernel<<<gemm_grid, 256, 0, s0>>>(gcn_w + 0 * F * F);
    cudaStreamWaitEvent(s0, evStruct, 0);
    agg_squash_kernel<<<agg_blocks, 256, 0, s0>>>(gcn_b + 0 * F, w_att + 0 * F);
    cudaEventRecord(evA0, s0);
    cudaStreamWaitEvent(s1, evA0, 0);
    readout_kernel<<<NG, F, 0, s1>>>(batch);      // overlaps gemm1
    cudaEventRecord(evR0, s1);

    // layer 1
    gemm_kernel<<<gemm_grid, 256, 0, s0>>>(gcn_w + 1 * F * F);
    cudaStreamWaitEvent(s0, evR0, 0);             // readout0 reads g_X before agg1 writes it
    agg_squash_kernel<<<agg_blocks, 256, 0, s0>>>(gcn_b + 1 * F, w_att + 1 * F);
    cudaEventRecord(evA1, s0);
    cudaStreamWaitEvent(s1, evA1, 0);
    readout_kernel<<<NG, F, 0, s1>>>(batch);      // overlaps gemm2
    cudaEventRecord(evR1, s1);

    // layer 2
    gemm_kernel<<<gemm_grid, 256, 0, s0>>>(gcn_w + 2 * F * F);
    cudaStreamWaitEvent(s0, evR1, 0);
    agg_squash_kernel<<<agg_blocks, 256, 0, s0>>>(gcn_b + 2 * F, w_att + 2 * F);
    readout_kernel<<<NG, F, 0, s0>>>(batch);

    mlp_kernel<<<NG, F, 0, s0>>>(lin1_w, lin1_b, lin2_w, lin2_b, out);
}

// round 6
// speedup vs baseline: 1.2913x; 1.0311x over previous
#include <cuda_runtime.h>
#include <cuda_bf16.h>
#include <mma.h>
#include <math.h>
#include <stdint.h>

using namespace nvcuda;

#define N_NODES 50000
#define N_EDGES 640000
#define F 128
#define NG 256
#define NC 10
#define NL 3

// ---------------- device scratch (no allocations allowed) ----------------
__device__ float g_X[N_NODES * F];     // current node features
__device__ float g_H[N_NODES * F];     // post-GEMM features
__device__ float g_att[N_NODES];
__device__ float g_dinv[N_NODES];
__device__ int   g_indeg[N_NODES];
__device__ int   g_rowptr[N_NODES + 1];
__device__ int   g_fill[N_NODES];
__device__ int   g_col[N_EDGES];
__device__ float g_stats[2 * F];
__device__ float g_bn_scale[F];
__device__ float g_bn_shift[F];
__device__ float g_rep[NG * 3 * F];
__device__ int   g_is64;

// ---------------- helpers ----------------
__device__ __forceinline__ float warp_sum(float v) {
    #pragma unroll
    for (int o = 16; o; o >>= 1) v += __shfl_xor_sync(0xffffffffu, v, o);
    return v;
}
__device__ __forceinline__ int load_idx(const void* p, long long i, int is64) {
    if (is64) return (int)((const long long*)p)[i];
    return ((const int*)p)[i];
}
// round-to-nearest tf32 (better than truncation the MMA would otherwise do)
__device__ __forceinline__ float f2tf32f(float x) {
    uint32_t u;
    asm("cvt.rna.tf32.f32 %0, %1;" : "=r"(u) : "f"(x));
    return __uint_as_float(u);
}

// ---------------- dtype detection ----------------
__global__ void detect_kernel(const void* ei) {
    if (threadIdx.x == 0) {
        const long long* p = (const long long*)ei;
        int ok64 = 1;
        for (int i = 0; i < 32; i++) {
            long long a = p[i];
            long long b = p[N_EDGES + i];
            if (a < 0 || a >= N_NODES || b < 0 || b >= N_NODES) { ok64 = 0; break; }
        }
        g_is64 = ok64;
    }
}

// ---------------- zero scratch ----------------
__global__ void zero_kernel() {
    int i = blockIdx.x * blockDim.x + threadIdx.x;
    int stride = gridDim.x * blockDim.x;
    for (int j = i; j < NG * 3 * F; j += stride) g_rep[j] = 0.0f;
    for (int j = i; j < N_NODES; j += stride) { g_indeg[j] = 0; g_fill[j] = 0; }
    for (int j = i; j < 2 * F; j += stride) g_stats[j] = 0.0f;
}

// ---------------- batchnorm ----------------
__global__ void bn_stats_kernel(const float* __restrict__ x) {
    int f = threadIdx.x;
    int r0 = blockIdx.x * 64;
    int r1 = min(r0 + 64, N_NODES);
    float s = 0.0f, s2 = 0.0f;
    for (int r = r0; r < r1; r++) {
        float v = x[r * F + f];
        s += v; s2 = fmaf(v, v, s2);
    }
    atomicAdd(&g_stats[f], s);
    atomicAdd(&g_stats[F + f], s2);
}

__global__ void bn_prep_kernel(const float* __restrict__ gamma,
                               const float* __restrict__ beta) {
    int f = threadIdx.x;
    float inv_n = 1.0f / (float)N_NODES;
    float mu = g_stats[f] * inv_n;
    float var = g_stats[F + f] * inv_n - mu * mu;
    float rstd = rsqrtf(var + 1e-5f);
    float s = gamma[f] * rstd;
    g_bn_scale[f] = s;
    g_bn_shift[f] = beta[f] - mu * s;
}

__global__ void bn_apply_kernel(const float* __restrict__ x) {
    int i = blockIdx.x * blockDim.x + threadIdx.x;
    int total4 = N_NODES * (F / 4);
    if (i >= total4) return;
    int f4 = i & (F / 4 - 1);
    float4 scl = ((const float4*)g_bn_scale)[f4];
    float4 sh  = ((const float4*)g_bn_shift)[f4];
    float4 v = ((const float4*)x)[i];
    v.x = fmaf(v.x, scl.x, sh.x);
    v.y = fmaf(v.y, scl.y, sh.y);
    v.z = fmaf(v.z, scl.z, sh.z);
    v.w = fmaf(v.w, scl.w, sh.w);
    ((float4*)g_X)[i] = v;
}

// ---------------- graph structure ----------------
__global__ void deg_count_kernel(const void* __restrict__ ei) {
    int e = blockIdx.x * blockDim.x + threadIdx.x;
    if (e >= N_EDGES) return;
    int is64 = g_is64;
    int s = load_idx(ei, e, is64);
    int d = load_idx(ei, (long long)N_EDGES + e, is64);
    if (s != d) atomicAdd(&g_indeg[d], 1);
}

__global__ void scan_kernel() {
    __shared__ int tot[1024];
    const int T = 1024;
    const int CH = (N_NODES + T - 1) / T;
    int t = threadIdx.x;
    int b = t * CH;
    int e = min(b + CH, N_NODES);
    int s = 0;
    for (int i = b; i < e; i++) s += g_indeg[i];
    tot[t] = s;
    __syncthreads();
    for (int off = 1; off < T; off <<= 1) {
        int v = (t >= off) ? tot[t - off] : 0;
        __syncthreads();
        tot[t] += v;
        __syncthreads();
    }
    int run = tot[t] - s;
    for (int i = b; i < e; i++) {
        g_rowptr[i] = run;
        run += g_indeg[i];
        g_dinv[i] = rsqrtf((float)(g_indeg[i] + 1));
    }
    if (t == 0) g_rowptr[N_NODES] = tot[T - 1];
}

__global__ void scatter_kernel(const void* __restrict__ ei) {
    int e = blockIdx.x * blockDim.x + threadIdx.x;
    if (e >= N_EDGES) return;
    int is64 = g_is64;
    int s = load_idx(ei, e, is64);
    int d = load_idx(ei, (long long)N_EDGES + e, is64);
    if (s != d) {
        int pos = g_rowptr[d] + atomicAdd(&g_fill[d], 1);
        g_col[pos] = s;
    }
}

// ---------------- wmma tf32 GEMM: g_H = g_X @ W  (128x128 tile, BK=32) --------
// 8 warps in 4x2: each warp computes 32x64 via 2x4 fragments of 16x16, K in 4
// chunks of 32 (4 k8 steps each). W is [k][n] row-major already.
__global__ __launch_bounds__(256) void gemm_wmma_kernel(const float* __restrict__ W) {
    const int m0 = blockIdx.x * 128;
    __shared__ __align__(16) float As[128][40];   // BK=32 + 8 skew
    __shared__ __align__(16) float Bs[32][136];   // 128 cols + 8 skew
    int tid = threadIdx.x;
    int wid = tid >> 5;
    int wm = wid >> 1;          // 0..3 -> warp row (32 rows each)
    int wn = wid & 1;           // 0..1 -> warp col (64 cols each)

    wmma::fragment<wmma::accumulator, 16, 16, 8, float> acc[2][4];
    #pragma unroll
    for (int i = 0; i < 2; i++)
        #pragma unroll
        for (int j = 0; j < 4; j++) wmma::fill_fragment(acc[i][j], 0.0f);

    for (int k0 = 0; k0 < 128; k0 += 32) {
        // A tile: 128 rows x 32 cols (1024 float4)
        #pragma unroll
        for (int t = 0; t < 4; t++) {
            int i = tid + t * 256;
            int r = i >> 3, c4 = i & 7;
            int gr = m0 + r;
            float4 v = (gr < N_NODES) ? ((const float4*)g_X)[gr * 32 + (k0 >> 2) + c4]
                                      : make_float4(0.f, 0.f, 0.f, 0.f);
            As[r][c4 * 4 + 0] = f2tf32f(v.x);
            As[r][c4 * 4 + 1] = f2tf32f(v.y);
            As[r][c4 * 4 + 2] = f2tf32f(v.z);
            As[r][c4 * 4 + 3] = f2tf32f(v.w);
        }
        // B tile: 32 rows x 128 cols (1024 float4)
        #pragma unroll
        for (int t = 0; t < 4; t++) {
            int i = tid + t * 256;
            int r = i >> 5, c4 = i & 31;
            float4 v = ((const float4*)W)[(k0 + r) * 32 + c4];
            Bs[r][c4 * 4 + 0] = f2tf32f(v.x);
            Bs[r][c4 * 4 + 1] = f2tf32f(v.y);
            Bs[r][c4 * 4 + 2] = f2tf32f(v.z);
            Bs[r][c4 * 4 + 3] = f2tf32f(v.w);
        }
        __syncthreads();

        #pragma unroll
        for (int kk = 0; kk < 32; kk += 8) {
            wmma::fragment<wmma::matrix_a, 16, 16, 8, wmma::precision::tf32, wmma::row_major> af[2];
            wmma::fragment<wmma::matrix_b, 16, 16, 8, wmma::precision::tf32, wmma::row_major> bf[4];
            #pragma unroll
            for (int i = 0; i < 2; i++)
                wmma::load_matrix_sync(af[i], &As[wm * 32 + i * 16][kk], 40);
            #pragma unroll
            for (int j = 0; j < 4; j++)
                wmma::load_matrix_sync(bf[j], &Bs[kk][wn * 64 + j * 16], 136);
            #pragma unroll
            for (int i = 0; i < 2; i++)
                #pragma unroll
                for (int j = 0; j < 4; j++)
                    wmma::mma_sync(acc[i][j], af[i], bf[j], acc[i][j]);
        }
        __syncthreads();
    }

    // N_NODES % 16 == 0, so 16-row blocks never straddle the edge
    #pragma unroll
    for (int i = 0; i < 2; i++) {
        int gr0 = m0 + wm * 32 + i * 16;
        if (gr0 + 16 <= N_NODES) {
            #pragma unroll
            for (int j = 0; j < 4; j++)
                wmma::store_matrix_sync(&g_H[gr0 * F + wn * 64 + j * 16], acc[i][j],
                                        F, wmma::mem_row_major);
        }
    }
}

// ---------------- aggregate + bias + squash + attention ----------------
__global__ __launch_bounds__(256) void agg_squash_kernel(const float* __restrict__ bias,
                                                         const float* __restrict__ watt) {
    int gtid = blockIdx.x * blockDim.x + threadIdx.x;
    int n = gtid >> 5;
    if (n >= N_NODES) return;
    int l = threadIdx.x & 31;

    const float4* __restrict__ H4 = (const float4*)g_H;
    float di = g_dinv[n];
    float4 hv = H4[n * 32 + l];
    float w = di * di;
    float4 acc = make_float4(w * hv.x, w * hv.y, w * hv.z, w * hv.w);

    int beg = g_rowptr[n], end = g_rowptr[n + 1];
    int e = beg;
    for (; e + 1 < end; e += 2) {
        int s0 = g_col[e], s1 = g_col[e + 1];
        float w0 = di * g_dinv[s0];
        float w1 = di * g_dinv[s1];
        float4 v0 = H4[s0 * 32 + l];
        float4 v1 = H4[s1 * 32 + l];
        acc.x = fmaf(w0, v0.x, acc.x); acc.x = fmaf(w1, v1.x, acc.x);
        acc.y = fmaf(w0, v0.y, acc.y); acc.y = fmaf(w1, v1.y, acc.y);
        acc.z = fmaf(w0, v0.z, acc.z); acc.z = fmaf(w1, v1.z, acc.z);
        acc.w = fmaf(w0, v0.w, acc.w); acc.w = fmaf(w1, v1.w, acc.w);
    }
    if (e < end) {
        int s0 = g_col[e];
        float w0 = di * g_dinv[s0];
        float4 v0 = H4[s0 * 32 + l];
        acc.x = fmaf(w0, v0.x, acc.x);
        acc.y = fmaf(w0, v0.y, acc.y);
        acc.z = fmaf(w0, v0.z, acc.z);
        acc.w = fmaf(w0, v0.w, acc.w);
    }
    float4 b4 = ((const float4*)bias)[l];
    acc.x += b4.x; acc.y += b4.y; acc.z += b4.z; acc.w += b4.w;

    float n2p = acc.x * acc.x + acc.y * acc.y + acc.z * acc.z + acc.w * acc.w;
    float n2 = warp_sum(n2p);
    float scl = (n2 / (1.0f + n2)) * rsqrtf(n2 + 1e-8f);
    float4 out = make_float4(scl * acc.x, scl * acc.y, scl * acc.z, scl * acc.w);
    ((float4*)g_X)[n * 32 + l] = out;

    float4 w4 = ((const float4*)watt)[l];
    float ap = out.x * w4.x + out.y * w4.y + out.z * w4.z + out.w * w4.w;
    float a = warp_sum(ap);
    if (l == 0) g_att[n] = a;
}

// ---------------- per-graph readout (batch is sorted; count = end-start) ------
__global__ void readout_kernel(const void* __restrict__ batch) {
    int g = blockIdx.x;
    int f = threadIdx.x;
    int is64 = g_is64;

    int lo = 0, hi = N_NODES;
    while (lo < hi) { int mid = (lo + hi) >> 1; if (load_idx(batch, mid, is64) < g) lo = mid + 1; else hi = mid; }
    int start = lo;
    lo = start; hi = N_NODES;
    while (lo < hi) { int mid = (lo + hi) >> 1; if (load_idx(batch, mid, is64) < g + 1) lo = mid + 1; else hi = mid; }
    int end = lo;

    float ws = 0.0f, sm = 0.0f, mx = -INFINITY;
    for (int n = start; n < end; n++) {
        float v = g_X[n * F + f];
        float a = g_att[n];
        ws = fmaf(a, v, ws);
        sm += v;
        mx = fmaxf(mx, v);
    }
    float cnt = fmaxf((float)(end - start), 1.0f);
    g_rep[g * 3 * F + f]         += ws;
    g_rep[g * 3 * F + F + f]     += sm / cnt;
    g_rep[g * 3 * F + 2 * F + f] += (start < end) ? mx : 0.0f;
}

// ---------------- final MLP + log_softmax ----------------
__global__ void mlp_kernel(const float* __restrict__ W1, const float* __restrict__ b1,
                           const float* __restrict__ W2, const float* __restrict__ b2,
                           float* __restrict__ out) {
    __shared__ float h[F];
    __shared__ float lg[NC];
    int g = blockIdx.x;
    int j = threadIdx.x;

    float acc = b1[j];
    const float* rep = &g_rep[g * 3 * F];
    for (int k = 0; k < 3 * F; k++)
        acc = fmaf(rep[k], W1[k * F + j], acc);
    h[j] = fmaxf(acc, 0.0f);
    __syncthreads();

    if (j < NC) {
        float l = b2[j];
        for (int k = 0; k < F; k++) l = fmaf(h[k], W2[k * NC + j], l);
        lg[j] = l;
    }
    __syncthreads();
    if (j < NC) {
        float m = -INFINITY;
        #pragma unroll
        for (int c = 0; c < NC; c++) m = fmaxf(m, lg[c]);
        float s = 0.0f;
        #pragma unroll
        for (int c = 0; c < NC; c++) s += expf(lg[c] - m);
        out[g * NC + j] = lg[j] - m - logf(s);
    }
}

// ---------------- launcher ----------------
extern "C" void kernel_launch(void* const* d_in, const int* in_sizes, int n_in,
                              void* d_out, int out_size) {
    const float* x      = (const float*)d_in[0];
    const void*  ei     = d_in[1];
    const void*  batch  = d_in[2];
    const float* gamma  = (const float*)d_in[3];
    const float* beta   = (const float*)d_in[4];
    const float* gcn_w  = (const float*)d_in[5];
    const float* gcn_b  = (const float*)d_in[6];
    const float* w_att  = (const float*)d_in[7];
    const float* lin1_w = (const float*)d_in[8];
    const float* lin1_b = (const float*)d_in[9];
    const float* lin2_w = (const float*)d_in[10];
    const float* lin2_b = (const float*)d_in[11];
    float* out = (float*)d_out;

    static cudaStream_t s1 = nullptr;
    static cudaEvent_t evFork, evStruct, evA0, evR0, evA1, evR1;
    if (!s1) {
        cudaStreamCreateWithFlags(&s1, cudaStreamNonBlocking);
        cudaEventCreateWithFlags(&evFork,   cudaEventDisableTiming);
        cudaEventCreateWithFlags(&evStruct, cudaEventDisableTiming);
        cudaEventCreateWithFlags(&evA0,     cudaEventDisableTiming);
        cudaEventCreateWithFlags(&evR0,     cudaEventDisableTiming);
        cudaEventCreateWithFlags(&evA1,     cudaEventDisableTiming);
        cudaEventCreateWithFlags(&evR1,     cudaEventDisableTiming);
    }
    cudaStream_t s0 = 0;

    detect_kernel<<<1, 32, 0, s0>>>(ei);
    zero_kernel<<<256, 256, 0, s0>>>();

    // fork structure build onto s1
    cudaEventRecord(evFork, s0);
    cudaStreamWaitEvent(s1, evFork, 0);
    deg_count_kernel<<<(N_EDGES + 255) / 256, 256, 0, s1>>>(ei);
    scan_kernel<<<1, 1024, 0, s1>>>();
    scatter_kernel<<<(N_EDGES + 255) / 256, 256, 0, s1>>>(ei);
    cudaEventRecord(evStruct, s1);

    // BN chain on s0
    bn_stats_kernel<<<(N_NODES + 63) / 64, 128, 0, s0>>>(x);
    bn_prep_kernel<<<1, F, 0, s0>>>(gamma, beta);
    bn_apply_kernel<<<(N_NODES * (F / 4) + 255) / 256, 256, 0, s0>>>(x);

    int gemm_grid = (N_NODES + 127) / 128;
    int agg_blocks = (N_NODES * 32 + 255) / 256;

    // layer 0
    gemm_wmma_kernel<<<gemm_grid, 256, 0, s0>>>(gcn_w + 0 * F * F);
    cudaStreamWaitEvent(s0, evStruct, 0);
    agg_squash_kernel<<<agg_blocks, 256, 0, s0>>>(gcn_b + 0 * F, w_att + 0 * F);
    cudaEventRecord(evA0, s0);
    cudaStreamWaitEvent(s1, evA0, 0);
    readout_kernel<<<NG, F, 0, s1>>>(batch);      // overlaps gemm1
    cudaEventRecord(evR0, s1);

    // layer 1
    gemm_wmma_kernel<<<gemm_grid, 256, 0, s0>>>(gcn_w + 1 * F * F);
    cudaStreamWaitEvent(s0, evR0, 0);
    agg_squash_kernel<<<agg_blocks, 256, 0, s0>>>(gcn_b + 1 * F, w_att + 1 * F);
    cudaEventRecord(evA1, s0);
    cudaStreamWaitEvent(s1, evA1, 0);
    readout_kernel<<<NG, F, 0, s1>>>(batch);      // overlaps gemm2
    cudaEventRecord(evR1, s1);

    // layer 2
    gemm_wmma_kernel<<<gemm_grid, 256, 0, s0>>>(gcn_w + 2 * F * F);
    cudaStreamWaitEvent(s0, evR1, 0);
    agg_squash_kernel<<<agg_blocks, 256, 0, s0>>>(gcn_b + 2 * F, w_att + 2 * F);
    readout_kernel<<<NG, F, 0, s0>>>(batch);

    mlp_kernel<<<NG, F, 0, s0>>>(lin1_w, lin1_b, lin2_w, lin2_b, out);
}

// round 7
// speedup vs baseline: 1.5560x; 1.2049x over previous
#include <cuda_runtime.h>
#include <cuda_bf16.h>
#include <mma.h>
#include <math.h>
#include <stdint.h>

using namespace nvcuda;

#define N_NODES 50000
#define N_EDGES 640000
#define F 128
#define NG 256
#define NC 10
#define NL 3
#define SCAN_BLOCKS 196   // 196 * 256 = 50176 >= 50000

// ---------------- device scratch (no allocations allowed) ----------------
__device__ float g_X[N_NODES * F];     // current node features
__device__ float g_H[N_NODES * F];     // post-GEMM features
__device__ float g_att[N_NODES];
__device__ float g_dinv[N_NODES];
__device__ int   g_indeg[N_NODES];
__device__ int   g_rowptr[N_NODES + 1];
__device__ int   g_fill[N_NODES];
__device__ int   g_col[N_EDGES];
__device__ int   g_btot[SCAN_BLOCKS];
__device__ int   g_boff[SCAN_BLOCKS];
__device__ float g_stats[2 * F];
__device__ float g_bn_scale[F];
__device__ float g_bn_shift[F];
__device__ float g_rep[NG * 3 * F];
__device__ int   g_is64;

// ---------------- helpers ----------------
__device__ __forceinline__ float warp_sum(float v) {
    #pragma unroll
    for (int o = 16; o; o >>= 1) v += __shfl_xor_sync(0xffffffffu, v, o);
    return v;
}
__device__ __forceinline__ int load_idx(const void* p, long long i, int is64) {
    if (is64) return (int)((const long long*)p)[i];
    return ((const int*)p)[i];
}
__device__ __forceinline__ float f2tf32f(float x) {
    uint32_t u;
    asm("cvt.rna.tf32.f32 %0, %1;" : "=r"(u) : "f"(x));
    return __uint_as_float(u);
}
// warp-inclusive scan
__device__ __forceinline__ int warp_iscan(int v, int lane) {
    #pragma unroll
    for (int o = 1; o < 32; o <<= 1) {
        int t = __shfl_up_sync(0xffffffffu, v, o);
        if (lane >= o) v += t;
    }
    return v;
}

// ---------------- dtype detection ----------------
__global__ void detect_kernel(const void* ei) {
    if (threadIdx.x == 0) {
        const long long* p = (const long long*)ei;
        int ok64 = 1;
        for (int i = 0; i < 32; i++) {
            long long a = p[i];
            long long b = p[N_EDGES + i];
            if (a < 0 || a >= N_NODES || b < 0 || b >= N_NODES) { ok64 = 0; break; }
        }
        g_is64 = ok64;
    }
}

// ---------------- zero scratch ----------------
__global__ void zero_kernel() {
    int i = blockIdx.x * blockDim.x + threadIdx.x;
    int stride = gridDim.x * blockDim.x;
    for (int j = i; j < NG * 3 * F; j += stride) g_rep[j] = 0.0f;
    for (int j = i; j < N_NODES; j += stride) { g_indeg[j] = 0; g_fill[j] = 0; }
    for (int j = i; j < 2 * F; j += stride) g_stats[j] = 0.0f;
}

// ---------------- batchnorm ----------------
__global__ void bn_stats_kernel(const float* __restrict__ x) {
    int f = threadIdx.x;
    int r0 = blockIdx.x * 64;
    int r1 = min(r0 + 64, N_NODES);
    float s = 0.0f, s2 = 0.0f;
    for (int r = r0; r < r1; r++) {
        float v = x[r * F + f];
        s += v; s2 = fmaf(v, v, s2);
    }
    atomicAdd(&g_stats[f], s);
    atomicAdd(&g_stats[F + f], s2);
}

__global__ void bn_prep_kernel(const float* __restrict__ gamma,
                               const float* __restrict__ beta) {
    int f = threadIdx.x;
    float inv_n = 1.0f / (float)N_NODES;
    float mu = g_stats[f] * inv_n;
    float var = g_stats[F + f] * inv_n - mu * mu;
    float rstd = rsqrtf(var + 1e-5f);
    float s = gamma[f] * rstd;
    g_bn_scale[f] = s;
    g_bn_shift[f] = beta[f] - mu * s;
}

__global__ void bn_apply_kernel(const float* __restrict__ x) {
    int i = blockIdx.x * blockDim.x + threadIdx.x;
    int total4 = N_NODES * (F / 4);
    if (i >= total4) return;
    int f4 = i & (F / 4 - 1);
    float4 scl = ((const float4*)g_bn_scale)[f4];
    float4 sh  = ((const float4*)g_bn_shift)[f4];
    float4 v = ((const float4*)x)[i];
    v.x = fmaf(v.x, scl.x, sh.x);
    v.y = fmaf(v.y, scl.y, sh.y);
    v.z = fmaf(v.z, scl.z, sh.z);
    v.w = fmaf(v.w, scl.w, sh.w);
    ((float4*)g_X)[i] = v;
}

// ---------------- graph structure ----------------
__global__ void deg_count_kernel(const void* __restrict__ ei) {
    int e = blockIdx.x * blockDim.x + threadIdx.x;
    if (e >= N_EDGES) return;
    int is64 = g_is64;
    int s = load_idx(ei, e, is64);
    int d = load_idx(ei, (long long)N_EDGES + e, is64);
    if (s != d) atomicAdd(&g_indeg[d], 1);
}

// -------- 3-phase device-wide exclusive scan of g_indeg -> g_rowptr ----------
__global__ void scan_phase1_kernel() {
    __shared__ int wtot[8];
    int t = threadIdx.x, lane = t & 31, w = t >> 5;
    int i = blockIdx.x * 256 + t;
    int v = (i < N_NODES) ? g_indeg[i] : 0;
    int incl = warp_iscan(v, lane);
    if (lane == 31) wtot[w] = incl;
    __syncthreads();
    if (w == 0) {
        int wv = (lane < 8) ? wtot[lane] : 0;
        wv = warp_iscan(wv, lane);
        if (lane < 8) wtot[lane] = wv;
    }
    __syncthreads();
    int base = (w > 0) ? wtot[w - 1] : 0;
    if (i < N_NODES) g_rowptr[i] = base + incl - v;   // block-local exclusive
    if (t == 255) g_btot[blockIdx.x] = base + incl;
}

__global__ void scan_phase2_kernel() {
    __shared__ int wtot[8];
    int t = threadIdx.x, lane = t & 31, w = t >> 5;
    int v = (t < SCAN_BLOCKS) ? g_btot[t] : 0;
    int incl = warp_iscan(v, lane);
    if (lane == 31) wtot[w] = incl;
    __syncthreads();
    if (w == 0) {
        int wv = (lane < 8) ? wtot[lane] : 0;
        wv = warp_iscan(wv, lane);
        if (lane < 8) wtot[lane] = wv;
    }
    __syncthreads();
    int base = (w > 0) ? wtot[w - 1] : 0;
    if (t < SCAN_BLOCKS) g_boff[t] = base + incl - v;  // exclusive block offset
    if (t == 255) g_rowptr[N_NODES] = wtot[7];
}

__global__ void scan_phase3_kernel() {
    int i = blockIdx.x * 256 + threadIdx.x;
    if (i >= N_NODES) return;
    g_rowptr[i] += g_boff[blockIdx.x];
    g_dinv[i] = rsqrtf((float)(g_indeg[i] + 1));
}

__global__ void scatter_kernel(const void* __restrict__ ei) {
    int e = blockIdx.x * blockDim.x + threadIdx.x;
    if (e >= N_EDGES) return;
    int is64 = g_is64;
    int s = load_idx(ei, e, is64);
    int d = load_idx(ei, (long long)N_EDGES + e, is64);
    if (s != d) {
        int pos = g_rowptr[d] + atomicAdd(&g_fill[d], 1);
        g_col[pos] = s;
    }
}

// ---------------- wmma tf32 GEMM: g_H = g_X @ W  (128x128 tile, BK=32) --------
__global__ __launch_bounds__(256) void gemm_wmma_kernel(const float* __restrict__ W) {
    const int m0 = blockIdx.x * 128;
    __shared__ __align__(16) float As[128][40];
    __shared__ __align__(16) float Bs[32][136];
    int tid = threadIdx.x;
    int wid = tid >> 5;
    int wm = wid >> 1;
    int wn = wid & 1;

    wmma::fragment<wmma::accumulator, 16, 16, 8, float> acc[2][4];
    #pragma unroll
    for (int i = 0; i < 2; i++)
        #pragma unroll
        for (int j = 0; j < 4; j++) wmma::fill_fragment(acc[i][j], 0.0f);

    for (int k0 = 0; k0 < 128; k0 += 32) {
        #pragma unroll
        for (int t = 0; t < 4; t++) {
            int i = tid + t * 256;
            int r = i >> 3, c4 = i & 7;
            int gr = m0 + r;
            float4 v = (gr < N_NODES) ? ((const float4*)g_X)[gr * 32 + (k0 >> 2) + c4]
                                      : make_float4(0.f, 0.f, 0.f, 0.f);
            As[r][c4 * 4 + 0] = f2tf32f(v.x);
            As[r][c4 * 4 + 1] = f2tf32f(v.y);
            As[r][c4 * 4 + 2] = f2tf32f(v.z);
            As[r][c4 * 4 + 3] = f2tf32f(v.w);
        }
        #pragma unroll
        for (int t = 0; t < 4; t++) {
            int i = tid + t * 256;
            int r = i >> 5, c4 = i & 31;
            float4 v = ((const float4*)W)[(k0 + r) * 32 + c4];
            Bs[r][c4 * 4 + 0] = f2tf32f(v.x);
            Bs[r][c4 * 4 + 1] = f2tf32f(v.y);
            Bs[r][c4 * 4 + 2] = f2tf32f(v.z);
            Bs[r][c4 * 4 + 3] = f2tf32f(v.w);
        }
        __syncthreads();

        #pragma unroll
        for (int kk = 0; kk < 32; kk += 8) {
            wmma::fragment<wmma::matrix_a, 16, 16, 8, wmma::precision::tf32, wmma::row_major> af[2];
            wmma::fragment<wmma::matrix_b, 16, 16, 8, wmma::precision::tf32, wmma::row_major> bf[4];
            #pragma unroll
            for (int i = 0; i < 2; i++)
                wmma::load_matrix_sync(af[i], &As[wm * 32 + i * 16][kk], 40);
            #pragma unroll
            for (int j = 0; j < 4; j++)
                wmma::load_matrix_sync(bf[j], &Bs[kk][wn * 64 + j * 16], 136);
            #pragma unroll
            for (int i = 0; i < 2; i++)
                #pragma unroll
                for (int j = 0; j < 4; j++)
                    wmma::mma_sync(acc[i][j], af[i], bf[j], acc[i][j]);
        }
        __syncthreads();
    }

    #pragma unroll
    for (int i = 0; i < 2; i++) {
        int gr0 = m0 + wm * 32 + i * 16;
        if (gr0 + 16 <= N_NODES) {
            #pragma unroll
            for (int j = 0; j < 4; j++)
                wmma::store_matrix_sync(&g_H[gr0 * F + wn * 64 + j * 16], acc[i][j],
                                        F, wmma::mem_row_major);
        }
    }
}

// ---------------- aggregate + bias + squash + attention ----------------
__global__ __launch_bounds__(256) void agg_squash_kernel(const float* __restrict__ bias,
                                                         const float* __restrict__ watt) {
    int gtid = blockIdx.x * blockDim.x + threadIdx.x;
    int n = gtid >> 5;
    if (n >= N_NODES) return;
    int l = threadIdx.x & 31;

    const float4* __restrict__ H4 = (const float4*)g_H;
    float di = g_dinv[n];
    float4 hv = H4[n * 32 + l];
    float w = di * di;
    float4 acc = make_float4(w * hv.x, w * hv.y, w * hv.z, w * hv.w);

    int beg = g_rowptr[n], end = g_rowptr[n + 1];
    int e = beg;
    for (; e + 1 < end; e += 2) {
        int s0 = g_col[e], s1 = g_col[e + 1];
        float w0 = di * g_dinv[s0];
        float w1 = di * g_dinv[s1];
        float4 v0 = H4[s0 * 32 + l];
        float4 v1 = H4[s1 * 32 + l];
        acc.x = fmaf(w0, v0.x, acc.x); acc.x = fmaf(w1, v1.x, acc.x);
        acc.y = fmaf(w0, v0.y, acc.y); acc.y = fmaf(w1, v1.y, acc.y);
        acc.z = fmaf(w0, v0.z, acc.z); acc.z = fmaf(w1, v1.z, acc.z);
        acc.w = fmaf(w0, v0.w, acc.w); acc.w = fmaf(w1, v1.w, acc.w);
    }
    if (e < end) {
        int s0 = g_col[e];
        float w0 = di * g_dinv[s0];
        float4 v0 = H4[s0 * 32 + l];
        acc.x = fmaf(w0, v0.x, acc.x);
        acc.y = fmaf(w0, v0.y, acc.y);
        acc.z = fmaf(w0, v0.z, acc.z);
        acc.w = fmaf(w0, v0.w, acc.w);
    }
    float4 b4 = ((const float4*)bias)[l];
    acc.x += b4.x; acc.y += b4.y; acc.z += b4.z; acc.w += b4.w;

    float n2p = acc.x * acc.x + acc.y * acc.y + acc.z * acc.z + acc.w * acc.w;
    float n2 = warp_sum(n2p);
    float scl = (n2 / (1.0f + n2)) * rsqrtf(n2 + 1e-8f);
    float4 out = make_float4(scl * acc.x, scl * acc.y, scl * acc.z, scl * acc.w);
    ((float4*)g_X)[n * 32 + l] = out;

    float4 w4 = ((const float4*)watt)[l];
    float ap = out.x * w4.x + out.y * w4.y + out.z * w4.z + out.w * w4.w;
    float a = warp_sum(ap);
    if (l == 0) g_att[n] = a;
}

// ---------------- per-graph readout (batch is sorted; count = end-start) ------
__global__ void readout_kernel(const void* __restrict__ batch) {
    int g = blockIdx.x;
    int f = threadIdx.x;
    int is64 = g_is64;

    int lo = 0, hi = N_NODES;
    while (lo < hi) { int mid = (lo + hi) >> 1; if (load_idx(batch, mid, is64) < g) lo = mid + 1; else hi = mid; }
    int start = lo;
    lo = start; hi = N_NODES;
    while (lo < hi) { int mid = (lo + hi) >> 1; if (load_idx(batch, mid, is64) < g + 1) lo = mid + 1; else hi = mid; }
    int end = lo;

    float ws = 0.0f, sm = 0.0f, mx = -INFINITY;
    for (int n = start; n < end; n++) {
        float v = g_X[n * F + f];
        float a = g_att[n];
        ws = fmaf(a, v, ws);
        sm += v;
        mx = fmaxf(mx, v);
    }
    float cnt = fmaxf((float)(end - start), 1.0f);
    g_rep[g * 3 * F + f]         += ws;
    g_rep[g * 3 * F + F + f]     += sm / cnt;
    g_rep[g * 3 * F + 2 * F + f] += (start < end) ? mx : 0.0f;
}

// ---------------- final MLP + log_softmax ----------------
__global__ void mlp_kernel(const float* __restrict__ W1, const float* __restrict__ b1,
                           const float* __restrict__ W2, const float* __restrict__ b2,
                           float* __restrict__ out) {
    __shared__ float h[F];
    __shared__ float lg[NC];
    int g = blockIdx.x;
    int j = threadIdx.x;

    float acc = b1[j];
    const float* rep = &g_rep[g * 3 * F];
    for (int k = 0; k < 3 * F; k++)
        acc = fmaf(rep[k], W1[k * F + j], acc);
    h[j] = fmaxf(acc, 0.0f);
    __syncthreads();

    if (j < NC) {
        float l = b2[j];
        for (int k = 0; k < F; k++) l = fmaf(h[k], W2[k * NC + j], l);
        lg[j] = l;
    }
    __syncthreads();
    if (j < NC) {
        float m = -INFINITY;
        #pragma unroll
        for (int c = 0; c < NC; c++) m = fmaxf(m, lg[c]);
        float s = 0.0f;
        #pragma unroll
        for (int c = 0; c < NC; c++) s += expf(lg[c] - m);
        out[g * NC + j] = lg[j] - m - logf(s);
    }
}

// ---------------- launcher ----------------
extern "C" void kernel_launch(void* const* d_in, const int* in_sizes, int n_in,
                              void* d_out, int out_size) {
    const float* x      = (const float*)d_in[0];
    const void*  ei     = d_in[1];
    const void*  batch  = d_in[2];
    const float* gamma  = (const float*)d_in[3];
    const float* beta   = (const float*)d_in[4];
    const float* gcn_w  = (const float*)d_in[5];
    const float* gcn_b  = (const float*)d_in[6];
    const float* w_att  = (const float*)d_in[7];
    const float* lin1_w = (const float*)d_in[8];
    const float* lin1_b = (const float*)d_in[9];
    const float* lin2_w = (const float*)d_in[10];
    const float* lin2_b = (const float*)d_in[11];
    float* out = (float*)d_out;

    static cudaStream_t s1 = nullptr;
    static cudaEvent_t evFork, evStruct, evA0, evR0, evA1, evR1;
    if (!s1) {
        cudaStreamCreateWithFlags(&s1, cudaStreamNonBlocking);
        cudaEventCreateWithFlags(&evFork,   cudaEventDisableTiming);
        cudaEventCreateWithFlags(&evStruct, cudaEventDisableTiming);
        cudaEventCreateWithFlags(&evA0,     cudaEventDisableTiming);
        cudaEventCreateWithFlags(&evR0,     cudaEventDisableTiming);
        cudaEventCreateWithFlags(&evA1,     cudaEventDisableTiming);
        cudaEventCreateWithFlags(&evR1,     cudaEventDisableTiming);
    }
    cudaStream_t s0 = 0;

    detect_kernel<<<1, 32, 0, s0>>>(ei);
    zero_kernel<<<256, 256, 0, s0>>>();

    // fork structure build onto s1
    cudaEventRecord(evFork, s0);
    cudaStreamWaitEvent(s1, evFork, 0);
    deg_count_kernel<<<(N_EDGES + 255) / 256, 256, 0, s1>>>(ei);
    scan_phase1_kernel<<<SCAN_BLOCKS, 256, 0, s1>>>();
    scan_phase2_kernel<<<1, 256, 0, s1>>>();
    scan_phase3_kernel<<<SCAN_BLOCKS, 256, 0, s1>>>();
    scatter_kernel<<<(N_EDGES + 255) / 256, 256, 0, s1>>>(ei);
    cudaEventRecord(evStruct, s1);

    // BN chain on s0
    bn_stats_kernel<<<(N_NODES + 63) / 64, 128, 0, s0>>>(x);
    bn_prep_kernel<<<1, F, 0, s0>>>(gamma, beta);
    bn_apply_kernel<<<(N_NODES * (F / 4) + 255) / 256, 256, 0, s0>>>(x);

    int gemm_grid = (N_NODES + 127) / 128;
    int agg_blocks = (N_NODES * 32 + 255) / 256;

    // layer 0
    gemm_wmma_kernel<<<gemm_grid, 256, 0, s0>>>(gcn_w + 0 * F * F);
    cudaStreamWaitEvent(s0, evStruct, 0);
    agg_squash_kernel<<<agg_blocks, 256, 0, s0>>>(gcn_b + 0 * F, w_att + 0 * F);
    cudaEventRecord(evA0, s0);
    cudaStreamWaitEvent(s1, evA0, 0);
    readout_kernel<<<NG, F, 0, s1>>>(batch);      // overlaps gemm1
    cudaEventRecord(evR0, s1);

    // layer 1
    gemm_wmma_kernel<<<gemm_grid, 256, 0, s0>>>(gcn_w + 1 * F * F);
    cudaStreamWaitEvent(s0, evR0, 0);
    agg_squash_kernel<<<agg_blocks, 256, 0, s0>>>(gcn_b + 1 * F, w_att + 1 * F);
    cudaEventRecord(evA1, s0);
    cudaStreamWaitEvent(s1, evA1, 0);
    readout_kernel<<<NG, F, 0, s1>>>(batch);      // overlaps gemm2
    cudaEventRecord(evR1, s1);

    // layer 2
    gemm_wmma_kernel<<<gemm_grid, 256, 0, s0>>>(gcn_w + 2 * F * F);
    cudaStreamWaitEvent(s0, evR1, 0);
    agg_squash_kernel<<<agg_blocks, 256, 0, s0>>>(gcn_b + 2 * F, w_att + 2 * F);
    readout_kernel<<<NG, F, 0, s0>>>(batch);

    mlp_kernel<<<NG, F, 0, s0>>>(lin1_w, lin1_b, lin2_w, lin2_b, out);
}

// round 11
// speedup vs baseline: 1.6843x; 1.0825x over previous
#include <cuda_runtime.h>
#include <cuda_fp16.h>
#include <mma.h>
#include <math.h>
#include <stdint.h>

using namespace nvcuda;

#define N_NODES 50000
#define N_EDGES 640000
#define F 128
#define NG 256
#define NC 10
#define NL 3
#define SCAN_BLOCKS 196   // 196 * 256 = 50176 >= 50000

// ---------------- device scratch (no allocations allowed) ----------------
__device__ float  g_X[N_NODES * F];      // current node features (fp32)
__device__ float  g_H[N_NODES * F];      // post-GEMM features (fp32)
__device__ float  g_att[N_NODES];
__device__ float  g_dinv[N_NODES];
__device__ int    g_indeg[N_NODES];
__device__ int    g_rowptr[N_NODES + 1];
__device__ int    g_fill[N_NODES];
__device__ int    g_col[N_EDGES];
__device__ int    g_btot[SCAN_BLOCKS];
__device__ int    g_boff[SCAN_BLOCKS];
__device__ float  g_stats[2 * F];
__device__ float  g_bn_scale[F];
__device__ float  g_bn_shift[F];
__device__ float  g_rep[NG * 3 * F];
__device__ int    g_is64;

// ---------------- helpers ----------------
__device__ __forceinline__ float warp_sum(float v) {
    #pragma unroll
    for (int o = 16; o; o >>= 1) v += __shfl_xor_sync(0xffffffffu, v, o);
    return v;
}
__device__ __forceinline__ int load_idx(const void* p, long long i, int is64) {
    if (is64) return (int)((const long long*)p)[i];
    return ((const int*)p)[i];
}
__device__ __forceinline__ float f2tf32f(float x) {
    uint32_t u;
    asm("cvt.rna.tf32.f32 %0, %1;" : "=r"(u) : "f"(x));
    return __uint_as_float(u);
}
__device__ __forceinline__ int warp_iscan(int v, int lane) {
    #pragma unroll
    for (int o = 1; o < 32; o <<= 1) {
        int t = __shfl_up_sync(0xffffffffu, v, o);
        if (lane >= o) v += t;
    }
    return v;
}

// ---------------- dtype detection ----------------
__global__ void detect_kernel(const void* ei) {
    if (threadIdx.x == 0) {
        const long long* p = (const long long*)ei;
        int ok64 = 1;
        for (int i = 0; i < 32; i++) {
            long long a = p[i];
            long long b = p[N_EDGES + i];
            if (a < 0 || a >= N_NODES || b < 0 || b >= N_NODES) { ok64 = 0; break; }
        }
        g_is64 = ok64;
    }
}

// ---------------- zero kernels ----------------
__global__ void zero_stats_kernel() {
    int i = threadIdx.x;
    if (i < 2 * F) g_stats[i] = 0.0f;
}
__global__ void zero_rest_kernel() {
    int i = blockIdx.x * blockDim.x + threadIdx.x;
    int stride = gridDim.x * blockDim.x;
    for (int j = i; j < NG * 3 * F; j += stride) g_rep[j] = 0.0f;
    for (int j = i; j < N_NODES; j += stride) { g_indeg[j] = 0; g_fill[j] = 0; }
}

// ---------------- batchnorm stats ----------------
__global__ void bn_stats_kernel(const float* __restrict__ x) {
    int f = threadIdx.x;
    int r0 = blockIdx.x * 64;
    int r1 = min(r0 + 64, N_NODES);
    float s = 0.0f, s2 = 0.0f;
    for (int r = r0; r < r1; r++) {
        float v = x[r * F + f];
        s += v; s2 = fmaf(v, v, s2);
    }
    atomicAdd(&g_stats[f], s);
    atomicAdd(&g_stats[F + f], s2);
}

__global__ void bn_prep_kernel(const float* __restrict__ gamma,
                               const float* __restrict__ beta) {
    int f = threadIdx.x;
    float inv_n = 1.0f / (float)N_NODES;
    float mu = g_stats[f] * inv_n;
    float var = g_stats[F + f] * inv_n - mu * mu;
    float rstd = rsqrtf(var + 1e-5f);
    float s = gamma[f] * rstd;
    g_bn_scale[f] = s;
    g_bn_shift[f] = beta[f] - mu * s;
}

// ---------------- graph structure ----------------
__global__ void deg_count_kernel(const void* __restrict__ ei) {
    int e = blockIdx.x * blockDim.x + threadIdx.x;
    if (e >= N_EDGES) return;
    int is64 = g_is64;
    int s = load_idx(ei, e, is64);
    int d = load_idx(ei, (long long)N_EDGES + e, is64);
    if (s != d) atomicAdd(&g_indeg[d], 1);
}

__global__ void scan_phase1_kernel() {
    __shared__ int wtot[8];
    int t = threadIdx.x, lane = t & 31, w = t >> 5;
    int i = blockIdx.x * 256 + t;
    int v = (i < N_NODES) ? g_indeg[i] : 0;
    int incl = warp_iscan(v, lane);
    if (lane == 31) wtot[w] = incl;
    __syncthreads();
    if (w == 0) {
        int wv = (lane < 8) ? wtot[lane] : 0;
        wv = warp_iscan(wv, lane);
        if (lane < 8) wtot[lane] = wv;
    }
    __syncthreads();
    int base = (w > 0) ? wtot[w - 1] : 0;
    if (i < N_NODES) g_rowptr[i] = base + incl - v;
    if (t == 255) g_btot[blockIdx.x] = base + incl;
}

__global__ void scan_phase2_kernel() {
    __shared__ int wtot[8];
    int t = threadIdx.x, lane = t & 31, w = t >> 5;
    int v = (t < SCAN_BLOCKS) ? g_btot[t] : 0;
    int incl = warp_iscan(v, lane);
    if (lane == 31) wtot[w] = incl;
    __syncthreads();
    if (w == 0) {
        int wv = (lane < 8) ? wtot[lane] : 0;
        wv = warp_iscan(wv, lane);
        if (lane < 8) wtot[lane] = wv;
    }
    __syncthreads();
    int base = (w > 0) ? wtot[w - 1] : 0;
    if (t < SCAN_BLOCKS) g_boff[t] = base + incl - v;
    if (t == 255) g_rowptr[N_NODES] = wtot[7];
}

__global__ void scan_phase3_kernel() {
    int i = blockIdx.x * 256 + threadIdx.x;
    if (i >= N_NODES) return;
    g_rowptr[i] += g_boff[blockIdx.x];
    g_dinv[i] = rsqrtf((float)(g_indeg[i] + 1));
}

__global__ void scatter_kernel(const void* __restrict__ ei) {
    int e = blockIdx.x * blockDim.x + threadIdx.x;
    if (e >= N_EDGES) return;
    int is64 = g_is64;
    int s = load_idx(ei, e, is64);
    int d = load_idx(ei, (long long)N_EDGES + e, is64);
    if (s != d) {
        int pos = g_rowptr[d] + atomicAdd(&g_fill[d], 1);
        g_col[pos] = s;
    }
}

// ---------------- wmma tf32 GEMM: g_H = src @ W  (128x128 tile, BK=32) --------
// use_bn != 0: read xin (harness input) and apply y = x*scale + shift inline.
// use_bn == 0: read the device-global g_X directly (device-side symbol — the
// host must NEVER pass &g_X: on GB300 ATS that silently reads the host shadow).
__global__ __launch_bounds__(256) void gemm_wmma_kernel(const float* __restrict__ xin,
                                                        const float* __restrict__ W,
                                                        int use_bn) {
    const int m0 = blockIdx.x * 128;
    __shared__ __align__(16) float As[128][40];
    __shared__ __align__(16) float Bs[32][136];
    int tid = threadIdx.x;
    int wid = tid >> 5;
    int wm = wid >> 1;
    int wn = wid & 1;

    const float4* __restrict__ a4 = use_bn ? (const float4*)xin : (const float4*)g_X;

    wmma::fragment<wmma::accumulator, 16, 16, 8, float> acc[2][4];
    #pragma unroll
    for (int i = 0; i < 2; i++)
        #pragma unroll
        for (int j = 0; j < 4; j++) wmma::fill_fragment(acc[i][j], 0.0f);

    for (int k0 = 0; k0 < 128; k0 += 32) {
        #pragma unroll
        for (int t = 0; t < 4; t++) {
            int i = tid + t * 256;
            int r = i >> 3, c4 = i & 7;
            int gr = m0 + r;
            float4 v = (gr < N_NODES) ? a4[gr * 32 + (k0 >> 2) + c4]
                                      : make_float4(0.f, 0.f, 0.f, 0.f);
            if (use_bn && gr < N_NODES) {
                float4 scl = ((const float4*)g_bn_scale)[(k0 >> 2) + c4];
                float4 sh  = ((const float4*)g_bn_shift)[(k0 >> 2) + c4];
                v.x = fmaf(v.x, scl.x, sh.x);
                v.y = fmaf(v.y, scl.y, sh.y);
                v.z = fmaf(v.z, scl.z, sh.z);
                v.w = fmaf(v.w, scl.w, sh.w);
            }
            As[r][c4 * 4 + 0] = f2tf32f(v.x);
            As[r][c4 * 4 + 1] = f2tf32f(v.y);
            As[r][c4 * 4 + 2] = f2tf32f(v.z);
            As[r][c4 * 4 + 3] = f2tf32f(v.w);
        }
        #pragma unroll
        for (int t = 0; t < 4; t++) {
            int i = tid + t * 256;
            int r = i >> 5, c4 = i & 31;
            float4 v = ((const float4*)W)[(k0 + r) * 32 + c4];
            Bs[r][c4 * 4 + 0] = f2tf32f(v.x);
            Bs[r][c4 * 4 + 1] = f2tf32f(v.y);
            Bs[r][c4 * 4 + 2] = f2tf32f(v.z);
            Bs[r][c4 * 4 + 3] = f2tf32f(v.w);
        }
        __syncthreads();

        #pragma unroll
        for (int kk = 0; kk < 32; kk += 8) {
            wmma::fragment<wmma::matrix_a, 16, 16, 8, wmma::precision::tf32, wmma::row_major> af[2];
            wmma::fragment<wmma::matrix_b, 16, 16, 8, wmma::precision::tf32, wmma::row_major> bf[4];
            #pragma unroll
            for (int i = 0; i < 2; i++)
                wmma::load_matrix_sync(af[i], &As[wm * 32 + i * 16][kk], 40);
            #pragma unroll
            for (int j = 0; j < 4; j++)
                wmma::load_matrix_sync(bf[j], &Bs[kk][wn * 64 + j * 16], 136);
            #pragma unroll
            for (int i = 0; i < 2; i++)
                #pragma unroll
                for (int j = 0; j < 4; j++)
                    wmma::mma_sync(acc[i][j], af[i], bf[j], acc[i][j]);
        }
        __syncthreads();
    }

    #pragma unroll
    for (int i = 0; i < 2; i++) {
        int gr0 = m0 + wm * 32 + i * 16;
        if (gr0 + 16 <= N_NODES) {
            #pragma unroll
            for (int j = 0; j < 4; j++)
                wmma::store_matrix_sync(&g_H[gr0 * F + wn * 64 + j * 16], acc[i][j],
                                        F, wmma::mem_row_major);
        }
    }
}

// ---------------- aggregate + bias + squash + attention (fp32 gather) ---------
__global__ __launch_bounds__(256) void agg_squash_kernel(const float* __restrict__ bias,
                                                         const float* __restrict__ watt) {
    int gtid = blockIdx.x * blockDim.x + threadIdx.x;
    int n = gtid >> 5;
    if (n >= N_NODES) return;
    int l = threadIdx.x & 31;

    const float4* __restrict__ H4 = (const float4*)g_H;
    float di = g_dinv[n];
    float4 hv = H4[n * 32 + l];
    float w = di * di;
    float4 acc = make_float4(w * hv.x, w * hv.y, w * hv.z, w * hv.w);

    int beg = g_rowptr[n], end = g_rowptr[n + 1];
    int e = beg;
    for (; e + 1 < end; e += 2) {
        int s0 = g_col[e], s1 = g_col[e + 1];
        float w0 = di * g_dinv[s0];
        float w1 = di * g_dinv[s1];
        float4 v0 = H4[s0 * 32 + l];
        float4 v1 = H4[s1 * 32 + l];
        acc.x = fmaf(w0, v0.x, acc.x); acc.x = fmaf(w1, v1.x, acc.x);
        acc.y = fmaf(w0, v0.y, acc.y); acc.y = fmaf(w1, v1.y, acc.y);
        acc.z = fmaf(w0, v0.z, acc.z); acc.z = fmaf(w1, v1.z, acc.z);
        acc.w = fmaf(w0, v0.w, acc.w); acc.w = fmaf(w1, v1.w, acc.w);
    }
    if (e < end) {
        int s0 = g_col[e];
        float w0 = di * g_dinv[s0];
        float4 v0 = H4[s0 * 32 + l];
        acc.x = fmaf(w0, v0.x, acc.x);
        acc.y = fmaf(w0, v0.y, acc.y);
        acc.z = fmaf(w0, v0.z, acc.z);
        acc.w = fmaf(w0, v0.w, acc.w);
    }
    float4 b4 = ((const float4*)bias)[l];
    acc.x += b4.x; acc.y += b4.y; acc.z += b4.z; acc.w += b4.w;

    float n2p = acc.x * acc.x + acc.y * acc.y + acc.z * acc.z + acc.w * acc.w;
    float n2 = warp_sum(n2p);
    float scl = (n2 / (1.0f + n2)) * rsqrtf(n2 + 1e-8f);
    float4 out = make_float4(scl * acc.x, scl * acc.y, scl * acc.z, scl * acc.w);
    ((float4*)g_X)[n * 32 + l] = out;

    float4 w4 = ((const float4*)watt)[l];
    float ap = out.x * w4.x + out.y * w4.y + out.z * w4.z + out.w * w4.w;
    float a = warp_sum(ap);
    if (l == 0) g_att[n] = a;
}

// ---------------- per-graph readout (sorted batch; 4-way node split) ----------
__global__ __launch_bounds__(512) void readout_kernel(const void* __restrict__ batch) {
    __shared__ float sws[4][F], ssm[4][F], smx[4][F];
    int g = blockIdx.x;
    int tid = threadIdx.x;
    int f = tid & 127;
    int part = tid >> 7;          // 0..3
    int is64 = g_is64;

    int lo = 0, hi = N_NODES;
    while (lo < hi) { int mid = (lo + hi) >> 1; if (load_idx(batch, mid, is64) < g) lo = mid + 1; else hi = mid; }
    int start = lo;
    lo = start; hi = N_NODES;
    while (lo < hi) { int mid = (lo + hi) >> 1; if (load_idx(batch, mid, is64) < g + 1) lo = mid + 1; else hi = mid; }
    int end = lo;

    float ws = 0.0f, sm = 0.0f, mx = -INFINITY;
    for (int n = start + part; n < end; n += 4) {
        float v = g_X[n * F + f];
        float a = g_att[n];
        ws = fmaf(a, v, ws);
        sm += v;
        mx = fmaxf(mx, v);
    }
    sws[part][f] = ws; ssm[part][f] = sm; smx[part][f] = mx;
    __syncthreads();
    if (part == 0) {
        #pragma unroll
        for (int p = 1; p < 4; p++) {
            ws += sws[p][f];
            sm += ssm[p][f];
            mx = fmaxf(mx, smx[p][f]);
        }
        float cnt = fmaxf((float)(end - start), 1.0f);
        g_rep[g * 3 * F + f]         += ws;
        g_rep[g * 3 * F + F + f]     += sm / cnt;
        g_rep[g * 3 * F + 2 * F + f] += (start < end) ? mx : 0.0f;
    }
}

// ---------------- final MLP + log_softmax ----------------
__global__ void mlp_kernel(const float* __restrict__ W1, const float* __restrict__ b1,
                           const float* __restrict__ W2, const float* __restrict__ b2,
                           float* __restrict__ out) {
    __shared__ float h[F];
    __shared__ float lg[NC];
    int g = blockIdx.x;
    int j = threadIdx.x;

    float acc = b1[j];
    const float* rep = &g_rep[g * 3 * F];
    for (int k = 0; k < 3 * F; k++)
        acc = fmaf(rep[k], W1[k * F + j], acc);
    h[j] = fmaxf(acc, 0.0f);
    __syncthreads();

    if (j < NC) {
        float l = b2[j];
        for (int k = 0; k < F; k++) l = fmaf(h[k], W2[k * NC + j], l);
        lg[j] = l;
    }
    __syncthreads();
    if (j < NC) {
        float m = -INFINITY;
        #pragma unroll
        for (int c = 0; c < NC; c++) m = fmaxf(m, lg[c]);
        float s = 0.0f;
        #pragma unroll
        for (int c = 0; c < NC; c++) s += expf(lg[c] - m);
        out[g * NC + j] = lg[j] - m - logf(s);
    }
}

// ---------------- launcher ----------------
extern "C" void kernel_launch(void* const* d_in, const int* in_sizes, int n_in,
                              void* d_out, int out_size) {
    const float* x      = (const float*)d_in[0];
    const void*  ei     = d_in[1];
    const void*  batch  = d_in[2];
    const float* gamma  = (const float*)d_in[3];
    const float* beta   = (const float*)d_in[4];
    const float* gcn_w  = (const float*)d_in[5];
    const float* gcn_b  = (const float*)d_in[6];
    const float* w_att  = (const float*)d_in[7];
    const float* lin1_w = (const float*)d_in[8];
    const float* lin1_b = (const float*)d_in[9];
    const float* lin2_w = (const float*)d_in[10];
    const float* lin2_b = (const float*)d_in[11];
    float* out = (float*)d_out;

    static cudaStream_t s1 = nullptr;
    static cudaEvent_t evFork, evStruct, evA0, evR0, evA1, evR1;
    if (!s1) {
        cudaStreamCreateWithFlags(&s1, cudaStreamNonBlocking);
        cudaEventCreateWithFlags(&evFork,   cudaEventDisableTiming);
        cudaEventCreateWithFlags(&evStruct, cudaEventDisableTiming);
        cudaEventCreateWithFlags(&evA0,     cudaEventDisableTiming);
        cudaEventCreateWithFlags(&evR0,     cudaEventDisableTiming);
        cudaEventCreateWithFlags(&evA1,     cudaEventDisableTiming);
        cudaEventCreateWithFlags(&evR1,     cudaEventDisableTiming);
    }
    cudaStream_t s0 = 0;

    // fork: detect + structure build + rep zero on s1; BN chain starts on s0
    cudaEventRecord(evFork, s0);
    cudaStreamWaitEvent(s1, evFork, 0);
    detect_kernel<<<1, 32, 0, s1>>>(ei);
    zero_rest_kernel<<<256, 256, 0, s1>>>();
    deg_count_kernel<<<(N_EDGES + 255) / 256, 256, 0, s1>>>(ei);
    scan_phase1_kernel<<<SCAN_BLOCKS, 256, 0, s1>>>();
    scan_phase2_kernel<<<1, 256, 0, s1>>>();
    scan_phase3_kernel<<<SCAN_BLOCKS, 256, 0, s1>>>();
    scatter_kernel<<<(N_EDGES + 255) / 256, 256, 0, s1>>>(ei);
    cudaEventRecord(evStruct, s1);

    zero_stats_kernel<<<1, 256, 0, s0>>>();
    bn_stats_kernel<<<(N_NODES + 63) / 64, 128, 0, s0>>>(x);
    bn_prep_kernel<<<1, F, 0, s0>>>(gamma, beta);

    int gemm_grid = (N_NODES + 127) / 128;
    int agg_blocks = (N_NODES * 32 + 255) / 256;

    // layer 0 (BN fused into A-load; kernel reads g_X internally when use_bn=0)
    gemm_wmma_kernel<<<gemm_grid, 256, 0, s0>>>(x, gcn_w + 0 * F * F, 1);
    cudaStreamWaitEvent(s0, evStruct, 0);
    agg_squash_kernel<<<agg_blocks, 256, 0, s0>>>(gcn_b + 0 * F, w_att + 0 * F);
    cudaEventRecord(evA0, s0);
    cudaStreamWaitEvent(s1, evA0, 0);
    readout_kernel<<<NG, 512, 0, s1>>>(batch);    // overlaps gemm1
    cudaEventRecord(evR0, s1);

    // layer 1
    gemm_wmma_kernel<<<gemm_grid, 256, 0, s0>>>(x, gcn_w + 1 * F * F, 0);
    cudaStreamWaitEvent(s0, evR0, 0);
    agg_squash_kernel<<<agg_blocks, 256, 0, s0>>>(gcn_b + 1 * F, w_att + 1 * F);
    cudaEventRecord(evA1, s0);
    cudaStreamWaitEvent(s1, evA1, 0);
    readout_kernel<<<NG, 512, 0, s1>>>(batch);    // overlaps gemm2
    cudaEventRecord(evR1, s1);

    // layer 2
    gemm_wmma_kernel<<<gemm_grid, 256, 0, s0>>>(x, gcn_w + 2 * F * F, 0);
    cudaStreamWaitEvent(s0, evR1, 0);
    agg_squash_kernel<<<agg_blocks, 256, 0, s0>>>(gcn_b + 2 * F, w_att + 2 * F);
    readout_kernel<<<NG, 512, 0, s0>>>(batch);

    mlp_kernel<<<NG, F, 0, s0>>>(lin1_w, lin1_b, lin2_w, lin2_b, out);
}

// round 12
// speedup vs baseline: 1.8764x; 1.1140x over previous
#include <cuda_runtime.h>
#include <cuda_fp16.h>
#include <mma.h>
#include <math.h>
#include <stdint.h>

using namespace nvcuda;

#define N_NODES 50000
#define N_EDGES 640000
#define F 128
#define NG 256
#define NC 10
#define NL 3
#define SCAN_BLOCKS 196   // 196 * 256 = 50176 >= 50000

// ---------------- device scratch (no allocations allowed) ----------------
__device__ float  g_X[N_NODES * F];      // current node features (fp32)
__device__ __half g_Hh[N_NODES * F];     // post-GEMM features (fp16; same mantissa as tf32)
__device__ float  g_att[N_NODES];
__device__ float  g_dinv[N_NODES];
__device__ int    g_indeg[N_NODES];
__device__ int    g_rowptr[N_NODES + 1];
__device__ int    g_fill[N_NODES];
__device__ int    g_col[N_EDGES];
__device__ int    g_btot[SCAN_BLOCKS];
__device__ int    g_boff[SCAN_BLOCKS];
__device__ float  g_stats[2 * F];
__device__ float  g_bn_scale[F];
__device__ float  g_bn_shift[F];
__device__ float  g_rep[NG * 3 * F];
__device__ int    g_is64;

// ---------------- helpers ----------------
__device__ __forceinline__ float warp_sum(float v) {
    #pragma unroll
    for (int o = 16; o; o >>= 1) v += __shfl_xor_sync(0xffffffffu, v, o);
    return v;
}
__device__ __forceinline__ int load_idx(const void* p, long long i, int is64) {
    if (is64) return (int)((const long long*)p)[i];
    return ((const int*)p)[i];
}
__device__ __forceinline__ float f2tf32f(float x) {
    uint32_t u;
    asm("cvt.rna.tf32.f32 %0, %1;" : "=r"(u) : "f"(x));
    return __uint_as_float(u);
}
__device__ __forceinline__ int warp_iscan(int v, int lane) {
    #pragma unroll
    for (int o = 1; o < 32; o <<= 1) {
        int t = __shfl_up_sync(0xffffffffu, v, o);
        if (lane >= o) v += t;
    }
    return v;
}

// ---------------- dtype detection ----------------
__global__ void detect_kernel(const void* ei) {
    if (threadIdx.x == 0) {
        const long long* p = (const long long*)ei;
        int ok64 = 1;
        for (int i = 0; i < 32; i++) {
            long long a = p[i];
            long long b = p[N_EDGES + i];
            if (a < 0 || a >= N_NODES || b < 0 || b >= N_NODES) { ok64 = 0; break; }
        }
        g_is64 = ok64;
    }
}

// ---------------- zero kernels ----------------
__global__ void zero_stats_kernel() {
    int i = threadIdx.x;
    if (i < 2 * F) g_stats[i] = 0.0f;
}
__global__ void zero_rest_kernel() {
    int i = blockIdx.x * blockDim.x + threadIdx.x;
    int stride = gridDim.x * blockDim.x;
    for (int j = i; j < NG * 3 * F; j += stride) g_rep[j] = 0.0f;
    for (int j = i; j < N_NODES; j += stride) { g_indeg[j] = 0; g_fill[j] = 0; }
}

// ---------------- batchnorm stats ----------------
__global__ void bn_stats_kernel(const float* __restrict__ x) {
    int f = threadIdx.x;
    int r0 = blockIdx.x * 64;
    int r1 = min(r0 + 64, N_NODES);
    float s = 0.0f, s2 = 0.0f;
    for (int r = r0; r < r1; r++) {
        float v = x[r * F + f];
        s += v; s2 = fmaf(v, v, s2);
    }
    atomicAdd(&g_stats[f], s);
    atomicAdd(&g_stats[F + f], s2);
}

__global__ void bn_prep_kernel(const float* __restrict__ gamma,
                               const float* __restrict__ beta) {
    int f = threadIdx.x;
    float inv_n = 1.0f / (float)N_NODES;
    float mu = g_stats[f] * inv_n;
    float var = g_stats[F + f] * inv_n - mu * mu;
    float rstd = rsqrtf(var + 1e-5f);
    float s = gamma[f] * rstd;
    g_bn_scale[f] = s;
    g_bn_shift[f] = beta[f] - mu * s;
}

// ---------------- graph structure ----------------
__global__ void deg_count_kernel(const void* __restrict__ ei) {
    int e = blockIdx.x * blockDim.x + threadIdx.x;
    if (e >= N_EDGES) return;
    int is64 = g_is64;
    int s = load_idx(ei, e, is64);
    int d = load_idx(ei, (long long)N_EDGES + e, is64);
    if (s != d) atomicAdd(&g_indeg[d], 1);
}

__global__ void scan_phase1_kernel() {
    __shared__ int wtot[8];
    int t = threadIdx.x, lane = t & 31, w = t >> 5;
    int i = blockIdx.x * 256 + t;
    int v = (i < N_NODES) ? g_indeg[i] : 0;
    int incl = warp_iscan(v, lane);
    if (lane == 31) wtot[w] = incl;
    __syncthreads();
    if (w == 0) {
        int wv = (lane < 8) ? wtot[lane] : 0;
        wv = warp_iscan(wv, lane);
        if (lane < 8) wtot[lane] = wv;
    }
    __syncthreads();
    int base = (w > 0) ? wtot[w - 1] : 0;
    if (i < N_NODES) g_rowptr[i] = base + incl - v;
    if (t == 255) g_btot[blockIdx.x] = base + incl;
}

__global__ void scan_phase2_kernel() {
    __shared__ int wtot[8];
    int t = threadIdx.x, lane = t & 31, w = t >> 5;
    int v = (t < SCAN_BLOCKS) ? g_btot[t] : 0;
    int incl = warp_iscan(v, lane);
    if (lane == 31) wtot[w] = incl;
    __syncthreads();
    if (w == 0) {
        int wv = (lane < 8) ? wtot[lane] : 0;
        wv = warp_iscan(wv, lane);
        if (lane < 8) wtot[lane] = wv;
    }
    __syncthreads();
    int base = (w > 0) ? wtot[w - 1] : 0;
    if (t < SCAN_BLOCKS) g_boff[t] = base + incl - v;
    if (t == 255) g_rowptr[N_NODES] = wtot[7];
}

__global__ void scan_phase3_kernel() {
    int i = blockIdx.x * 256 + threadIdx.x;
    if (i >= N_NODES) return;
    g_rowptr[i] += g_boff[blockIdx.x];
    g_dinv[i] = rsqrtf((float)(g_indeg[i] + 1));
}

__global__ void scatter_kernel(const void* __restrict__ ei) {
    int e = blockIdx.x * blockDim.x + threadIdx.x;
    if (e >= N_EDGES) return;
    int is64 = g_is64;
    int s = load_idx(ei, e, is64);
    int d = load_idx(ei, (long long)N_EDGES + e, is64);
    if (s != d) {
        int pos = g_rowptr[d] + atomicAdd(&g_fill[d], 1);
        g_col[pos] = s;
    }
}

// ---------------- wmma tf32 GEMM: g_Hh = src @ W  (128x128 tile, BK=32) -------
// use_bn != 0: read xin (harness input) and apply y = x*scale + shift inline.
// use_bn == 0: read device-global g_X (device-side symbol only — the host must
// NEVER pass &g_X: on GB300 ATS that silently reads the host shadow).
// Output converted to fp16 via per-warp smem staging.
__global__ __launch_bounds__(256) void gemm_wmma_kernel(const float* __restrict__ xin,
                                                        const float* __restrict__ W,
                                                        int use_bn) {
    const int m0 = blockIdx.x * 128;
    __shared__ __align__(16) float As[128][40];
    __shared__ __align__(16) float Bs[32][136];
    int tid = threadIdx.x;
    int wid = tid >> 5;
    int lane = tid & 31;
    int wm = wid >> 1;
    int wn = wid & 1;

    const float4* __restrict__ a4 = use_bn ? (const float4*)xin : (const float4*)g_X;

    wmma::fragment<wmma::accumulator, 16, 16, 8, float> acc[2][4];
    #pragma unroll
    for (int i = 0; i < 2; i++)
        #pragma unroll
        for (int j = 0; j < 4; j++) wmma::fill_fragment(acc[i][j], 0.0f);

    for (int k0 = 0; k0 < 128; k0 += 32) {
        #pragma unroll
        for (int t = 0; t < 4; t++) {
            int i = tid + t * 256;
            int r = i >> 3, c4 = i & 7;
            int gr = m0 + r;
            float4 v = (gr < N_NODES) ? a4[gr * 32 + (k0 >> 2) + c4]
                                      : make_float4(0.f, 0.f, 0.f, 0.f);
            if (use_bn && gr < N_NODES) {
                float4 scl = ((const float4*)g_bn_scale)[(k0 >> 2) + c4];
                float4 sh  = ((const float4*)g_bn_shift)[(k0 >> 2) + c4];
                v.x = fmaf(v.x, scl.x, sh.x);
                v.y = fmaf(v.y, scl.y, sh.y);
                v.z = fmaf(v.z, scl.z, sh.z);
                v.w = fmaf(v.w, scl.w, sh.w);
            }
            As[r][c4 * 4 + 0] = f2tf32f(v.x);
            As[r][c4 * 4 + 1] = f2tf32f(v.y);
            As[r][c4 * 4 + 2] = f2tf32f(v.z);
            As[r][c4 * 4 + 3] = f2tf32f(v.w);
        }
        #pragma unroll
        for (int t = 0; t < 4; t++) {
            int i = tid + t * 256;
            int r = i >> 5, c4 = i & 31;
            float4 v = ((const float4*)W)[(k0 + r) * 32 + c4];
            Bs[r][c4 * 4 + 0] = f2tf32f(v.x);
            Bs[r][c4 * 4 + 1] = f2tf32f(v.y);
            Bs[r][c4 * 4 + 2] = f2tf32f(v.z);
            Bs[r][c4 * 4 + 3] = f2tf32f(v.w);
        }
        __syncthreads();

        #pragma unroll
        for (int kk = 0; kk < 32; kk += 8) {
            wmma::fragment<wmma::matrix_a, 16, 16, 8, wmma::precision::tf32, wmma::row_major> af[2];
            wmma::fragment<wmma::matrix_b, 16, 16, 8, wmma::precision::tf32, wmma::row_major> bf[4];
            #pragma unroll
            for (int i = 0; i < 2; i++)
                wmma::load_matrix_sync(af[i], &As[wm * 32 + i * 16][kk], 40);
            #pragma unroll
            for (int j = 0; j < 4; j++)
                wmma::load_matrix_sync(bf[j], &Bs[kk][wn * 64 + j * 16], 136);
            #pragma unroll
            for (int i = 0; i < 2; i++)
                #pragma unroll
                for (int j = 0; j < 4; j++)
                    wmma::mma_sync(acc[i][j], af[i], bf[j], acc[i][j]);
        }
        __syncthreads();
    }

    // epilogue: stage each 16x16 fragment through smem, convert to fp16, store
    float* stage = &As[0][0] + wid * 320;     // 16 rows x ld 20 per warp
    #pragma unroll
    for (int i = 0; i < 2; i++) {
        int gr0 = m0 + wm * 32 + i * 16;
        if (gr0 + 16 <= N_NODES) {
            #pragma unroll
            for (int j = 0; j < 4; j++) {
                wmma::store_matrix_sync(stage, acc[i][j], 20, wmma::mem_row_major);
                __syncwarp();
                int r = lane >> 1, cc = (lane & 1) * 8;
                float4 v0 = *(float4*)&stage[r * 20 + cc];
                float4 v1 = *(float4*)&stage[r * 20 + cc + 4];
                __half2 h0 = __floats2half2_rn(v0.x, v0.y);
                __half2 h1 = __floats2half2_rn(v0.z, v0.w);
                __half2 h2 = __floats2half2_rn(v1.x, v1.y);
                __half2 h3 = __floats2half2_rn(v1.z, v1.w);
                uint4 u;
                u.x = *(uint32_t*)&h0; u.y = *(uint32_t*)&h1;
                u.z = *(uint32_t*)&h2; u.w = *(uint32_t*)&h3;
                *(uint4*)&g_Hh[(gr0 + r) * F + wn * 64 + j * 16 + cc] = u;
                __syncwarp();
            }
        }
    }
}

// ---------------- aggregate + bias + squash + attention (fp16 gather) ---------
__global__ __launch_bounds__(256) void agg_squash_kernel(const float* __restrict__ bias,
                                                         const float* __restrict__ watt) {
    int gtid = blockIdx.x * blockDim.x + threadIdx.x;
    int n = gtid >> 5;
    if (n >= N_NODES) return;
    int l = threadIdx.x & 31;

    const uint2* __restrict__ H2 = (const uint2*)g_Hh;
    float di = g_dinv[n];
    float w = di * di;                       // self loop weight

    uint2 su = H2[n * 32 + l];
    __half2* sp = (__half2*)&su;
    float2 s0f = __half22float2(sp[0]);
    float2 s1f = __half22float2(sp[1]);
    float4 acc = make_float4(w * s0f.x, w * s0f.y, w * s1f.x, w * s1f.y);

    int beg = g_rowptr[n], end = g_rowptr[n + 1];
    int e = beg;
    for (; e + 1 < end; e += 2) {
        int n0 = g_col[e], n1 = g_col[e + 1];
        float w0 = di * g_dinv[n0];
        float w1 = di * g_dinv[n1];
        uint2 u0 = H2[n0 * 32 + l];
        uint2 u1 = H2[n1 * 32 + l];
        __half2* p0 = (__half2*)&u0;
        __half2* p1 = (__half2*)&u1;
        float2 a0 = __half22float2(p0[0]), a1 = __half22float2(p0[1]);
        float2 b0 = __half22float2(p1[0]), b1 = __half22float2(p1[1]);
        acc.x = fmaf(w0, a0.x, acc.x); acc.x = fmaf(w1, b0.x, acc.x);
        acc.y = fmaf(w0, a0.y, acc.y); acc.y = fmaf(w1, b0.y, acc.y);
        acc.z = fmaf(w0, a1.x, acc.z); acc.z = fmaf(w1, b1.x, acc.z);
        acc.w = fmaf(w0, a1.y, acc.w); acc.w = fmaf(w1, b1.y, acc.w);
    }
    if (e < end) {
        int n0 = g_col[e];
        float w0 = di * g_dinv[n0];
        uint2 u0 = H2[n0 * 32 + l];
        __half2* p0 = (__half2*)&u0;
        float2 a0 = __half22float2(p0[0]), a1 = __half22float2(p0[1]);
        acc.x = fmaf(w0, a0.x, acc.x);
        acc.y = fmaf(w0, a0.y, acc.y);
        acc.z = fmaf(w0, a1.x, acc.z);
        acc.w = fmaf(w0, a1.y, acc.w);
    }
    float4 b4 = ((const float4*)bias)[l];
    acc.x += b4.x; acc.y += b4.y; acc.z += b4.z; acc.w += b4.w;

    float n2p = acc.x * acc.x + acc.y * acc.y + acc.z * acc.z + acc.w * acc.w;
    float n2 = warp_sum(n2p);
    float scl = (n2 / (1.0f + n2)) * rsqrtf(n2 + 1e-8f);
    float4 out = make_float4(scl * acc.x, scl * acc.y, scl * acc.z, scl * acc.w);
    ((float4*)g_X)[n * 32 + l] = out;

    float4 w4 = ((const float4*)watt)[l];
    float ap = out.x * w4.x + out.y * w4.y + out.z * w4.z + out.w * w4.w;
    float a = warp_sum(ap);
    if (l == 0) g_att[n] = a;
}

// ---------------- per-graph readout (sorted batch; 4-way node split) ----------
__global__ __launch_bounds__(512) void readout_kernel(const void* __restrict__ batch) {
    __shared__ float sws[4][F], ssm[4][F], smx[4][F];
    int g = blockIdx.x;
    int tid = threadIdx.x;
    int f = tid & 127;
    int part = tid >> 7;          // 0..3
    int is64 = g_is64;

    int lo = 0, hi = N_NODES;
    while (lo < hi) { int mid = (lo + hi) >> 1; if (load_idx(batch, mid, is64) < g) lo = mid + 1; else hi = mid; }
    int start = lo;
    lo = start; hi = N_NODES;
    while (lo < hi) { int mid = (lo + hi) >> 1; if (load_idx(batch, mid, is64) < g + 1) lo = mid + 1; else hi = mid; }
    int end = lo;

    float ws = 0.0f, sm = 0.0f, mx = -INFINITY;
    for (int n = start + part; n < end; n += 4) {
        float v = g_X[n * F + f];
        float a = g_att[n];
        ws = fmaf(a, v, ws);
        sm += v;
        mx = fmaxf(mx, v);
    }
    sws[part][f] = ws; ssm[part][f] = sm; smx[part][f] = mx;
    __syncthreads();
    if (part == 0) {
        #pragma unroll
        for (int p = 1; p < 4; p++) {
            ws += sws[p][f];
            sm += ssm[p][f];
            mx = fmaxf(mx, smx[p][f]);
        }
        float cnt = fmaxf((float)(end - start), 1.0f);
        g_rep[g * 3 * F + f]         += ws;
        g_rep[g * 3 * F + F + f]     += sm / cnt;
        g_rep[g * 3 * F + 2 * F + f] += (start < end) ? mx : 0.0f;
    }
}

// ---------------- final MLP + log_softmax ----------------
__global__ void mlp_kernel(const float* __restrict__ W1, const float* __restrict__ b1,
                           const float* __restrict__ W2, const float* __restrict__ b2,
                           float* __restrict__ out) {
    __shared__ float h[F];
    __shared__ float lg[NC];
    int g = blockIdx.x;
    int j = threadIdx.x;

    float acc = b1[j];
    const float* rep = &g_rep[g * 3 * F];
    for (int k = 0; k < 3 * F; k++)
        acc = fmaf(rep[k], W1[k * F + j], acc);
    h[j] = fmaxf(acc, 0.0f);
    __syncthreads();

    if (j < NC) {
        float l = b2[j];
        for (int k = 0; k < F; k++) l = fmaf(h[k], W2[k * NC + j], l);
        lg[j] = l;
    }
    __syncthreads();
    if (j < NC) {
        float m = -INFINITY;
        #pragma unroll
        for (int c = 0; c < NC; c++) m = fmaxf(m, lg[c]);
        float s = 0.0f;
        #pragma unroll
        for (int c = 0; c < NC; c++) s += expf(lg[c] - m);
        out[g * NC + j] = lg[j] - m - logf(s);
    }
}

// ---------------- launcher ----------------
extern "C" void kernel_launch(void* const* d_in, const int* in_sizes, int n_in,
                              void* d_out, int out_size) {
    const float* x      = (const float*)d_in[0];
    const void*  ei     = d_in[1];
    const void*  batch  = d_in[2];
    const float* gamma  = (const float*)d_in[3];
    const float* beta   = (const float*)d_in[4];
    const float* gcn_w  = (const float*)d_in[5];
    const float* gcn_b  = (const float*)d_in[6];
    const float* w_att  = (const float*)d_in[7];
    const float* lin1_w = (const float*)d_in[8];
    const float* lin1_b = (const float*)d_in[9];
    const float* lin2_w = (const float*)d_in[10];
    const float* lin2_b = (const float*)d_in[11];
    float* out = (float*)d_out;

    static cudaStream_t s1 = nullptr;
    static cudaEvent_t evFork, evStruct, evA0, evR0, evA1, evR1;
    if (!s1) {
        cudaStreamCreateWithFlags(&s1, cudaStreamNonBlocking);
        cudaEventCreateWithFlags(&evFork,   cudaEventDisableTiming);
        cudaEventCreateWithFlags(&evStruct, cudaEventDisableTiming);
        cudaEventCreateWithFlags(&evA0,     cudaEventDisableTiming);
        cudaEventCreateWithFlags(&evR0,     cudaEventDisableTiming);
        cudaEventCreateWithFlags(&evA1,     cudaEventDisableTiming);
        cudaEventCreateWithFlags(&evR1,     cudaEventDisableTiming);
    }
    cudaStream_t s0 = 0;

    // fork: detect + structure build + rep zero on s1; BN chain starts on s0
    cudaEventRecord(evFork, s0);
    cudaStreamWaitEvent(s1, evFork, 0);
    detect_kernel<<<1, 32, 0, s1>>>(ei);
    zero_rest_kernel<<<256, 256, 0, s1>>>();
    deg_count_kernel<<<(N_EDGES + 255) / 256, 256, 0, s1>>>(ei);
    scan_phase1_kernel<<<SCAN_BLOCKS, 256, 0, s1>>>();
    scan_phase2_kernel<<<1, 256, 0, s1>>>();
    scan_phase3_kernel<<<SCAN_BLOCKS, 256, 0, s1>>>();
    scatter_kernel<<<(N_EDGES + 255) / 256, 256, 0, s1>>>(ei);
    cudaEventRecord(evStruct, s1);

    zero_stats_kernel<<<1, 256, 0, s0>>>();
    bn_stats_kernel<<<(N_NODES + 63) / 64, 128, 0, s0>>>(x);
    bn_prep_kernel<<<1, F, 0, s0>>>(gamma, beta);

    int gemm_grid = (N_NODES + 127) / 128;
    int agg_blocks = (N_NODES * 32 + 255) / 256;

    // layer 0 (BN fused into A-load; kernel reads g_X internally when use_bn=0)
    gemm_wmma_kernel<<<gemm_grid, 256, 0, s0>>>(x, gcn_w + 0 * F * F, 1);
    cudaStreamWaitEvent(s0, evStruct, 0);
    agg_squash_kernel<<<agg_blocks, 256, 0, s0>>>(gcn_b + 0 * F, w_att + 0 * F);
    cudaEventRecord(evA0, s0);
    cudaStreamWaitEvent(s1, evA0, 0);
    readout_kernel<<<NG, 512, 0, s1>>>(batch);    // overlaps gemm1
    cudaEventRecord(evR0, s1);

    // layer 1
    gemm_wmma_kernel<<<gemm_grid, 256, 0, s0>>>(x, gcn_w + 1 * F * F, 0);
    cudaStreamWaitEvent(s0, evR0, 0);
    agg_squash_kernel<<<agg_blocks, 256, 0, s0>>>(gcn_b + 1 * F, w_att + 1 * F);
    cudaEventRecord(evA1, s0);
    cudaStreamWaitEvent(s1, evA1, 0);
    readout_kernel<<<NG, 512, 0, s1>>>(batch);    // overlaps gemm2
    cudaEventRecord(evR1, s1);

    // layer 2
    gemm_wmma_kernel<<<gemm_grid, 256, 0, s0>>>(x, gcn_w + 2 * F * F, 0);
    cudaStreamWaitEvent(s0, evR1, 0);
    agg_squash_kernel<<<agg_blocks, 256, 0, s0>>>(gcn_b + 2 * F, w_att + 2 * F);
    readout_kernel<<<NG, 512, 0, s0>>>(batch);

    mlp_kernel<<<NG, F, 0, s0>>>(lin1_w, lin1_b, lin2_w, lin2_b, out);
}

// round 14
// speedup vs baseline: 1.9317x; 1.0295x over previous
#include <cuda_runtime.h>
#include <cuda_fp16.h>
#include <mma.h>
#include <math.h>
#include <stdint.h>

using namespace nvcuda;

#define N_NODES 50000
#define N_EDGES 640000
#define F 128
#define NG 256
#define NC 10
#define NL 3
#define SCAN_BLOCKS 196   // 196 * 256 = 50176 >= 50000

// ---------------- device scratch (no allocations allowed) ----------------
__device__ __half g_Xh[N_NODES * F];     // current node features (fp16 = tf32 mantissa)
__device__ __half g_Hh[N_NODES * F];     // post-GEMM features (fp16)
__device__ float  g_att[N_NODES];
__device__ float  g_dinv[N_NODES];
__device__ int    g_indeg[N_NODES];
__device__ int    g_rowptr[N_NODES + 1];
__device__ int    g_fill[N_NODES];
__device__ int    g_col[N_EDGES];
__device__ int    g_btot[SCAN_BLOCKS];
__device__ int    g_boff[SCAN_BLOCKS];
__device__ float  g_stats[2 * F];
__device__ float  g_bn_scale[F];
__device__ float  g_bn_shift[F];
__device__ float  g_rep[NG * 3 * F];
__device__ int    g_is64;

// ---------------- helpers ----------------
__device__ __forceinline__ float warp_sum(float v) {
    #pragma unroll
    for (int o = 16; o; o >>= 1) v += __shfl_xor_sync(0xffffffffu, v, o);
    return v;
}
__device__ __forceinline__ int load_idx(const void* p, long long i, int is64) {
    if (is64) return (int)((const long long*)p)[i];
    return ((const int*)p)[i];
}
__device__ __forceinline__ float f2tf32f(float x) {
    uint32_t u;
    asm("cvt.rna.tf32.f32 %0, %1;" : "=r"(u) : "f"(x));
    return __uint_as_float(u);
}
__device__ __forceinline__ int warp_iscan(int v, int lane) {
    #pragma unroll
    for (int o = 1; o < 32; o <<= 1) {
        int t = __shfl_up_sync(0xffffffffu, v, o);
        if (lane >= o) v += t;
    }
    return v;
}

// ---------------- init: zero scratch + dtype detect (merged) ----------------
__global__ void init_rest_kernel(const void* ei) {
    int i = blockIdx.x * blockDim.x + threadIdx.x;
    int stride = gridDim.x * blockDim.x;
    if (blockIdx.x == 0 && threadIdx.x == 0) {
        const long long* p = (const long long*)ei;
        int ok64 = 1;
        for (int k = 0; k < 32; k++) {
            long long a = p[k];
            long long b = p[N_EDGES + k];
            if (a < 0 || a >= N_NODES || b < 0 || b >= N_NODES) { ok64 = 0; break; }
        }
        g_is64 = ok64;
    }
    for (int j = i; j < NG * 3 * F; j += stride) g_rep[j] = 0.0f;
    for (int j = i; j < N_NODES; j += stride) { g_indeg[j] = 0; g_fill[j] = 0; }
}

__global__ void zero_stats_kernel() {
    int i = threadIdx.x;
    if (i < 2 * F) g_stats[i] = 0.0f;
}

// ---------------- batchnorm stats ----------------
__global__ void bn_stats_kernel(const float* __restrict__ x) {
    int f = threadIdx.x;
    int r0 = blockIdx.x * 64;
    int r1 = min(r0 + 64, N_NODES);
    float s = 0.0f, s2 = 0.0f;
    for (int r = r0; r < r1; r++) {
        float v = x[r * F + f];
        s += v; s2 = fmaf(v, v, s2);
    }
    atomicAdd(&g_stats[f], s);
    atomicAdd(&g_stats[F + f], s2);
}

__global__ void bn_prep_kernel(const float* __restrict__ gamma,
                               const float* __restrict__ beta) {
    int f = threadIdx.x;
    float inv_n = 1.0f / (float)N_NODES;
    float mu = g_stats[f] * inv_n;
    float var = g_stats[F + f] * inv_n - mu * mu;
    float rstd = rsqrtf(var + 1e-5f);
    float s = gamma[f] * rstd;
    g_bn_scale[f] = s;
    g_bn_shift[f] = beta[f] - mu * s;
}

// ---------------- graph structure ----------------
__global__ void deg_count_kernel(const void* __restrict__ ei) {
    int e = blockIdx.x * blockDim.x + threadIdx.x;
    if (e >= N_EDGES) return;
    int is64 = g_is64;
    int s = load_idx(ei, e, is64);
    int d = load_idx(ei, (long long)N_EDGES + e, is64);
    if (s != d) atomicAdd(&g_indeg[d], 1);
}

__global__ void scan_phase1_kernel() {
    __shared__ int wtot[8];
    int t = threadIdx.x, lane = t & 31, w = t >> 5;
    int i = blockIdx.x * 256 + t;
    int v = (i < N_NODES) ? g_indeg[i] : 0;
    int incl = warp_iscan(v, lane);
    if (lane == 31) wtot[w] = incl;
    __syncthreads();
    if (w == 0) {
        int wv = (lane < 8) ? wtot[lane] : 0;
        wv = warp_iscan(wv, lane);
        if (lane < 8) wtot[lane] = wv;
    }
    __syncthreads();
    int base = (w > 0) ? wtot[w - 1] : 0;
    if (i < N_NODES) g_rowptr[i] = base + incl - v;
    if (t == 255) g_btot[blockIdx.x] = base + incl;
}

__global__ void scan_phase2_kernel() {
    __shared__ int wtot[8];
    int t = threadIdx.x, lane = t & 31, w = t >> 5;
    int v = (t < SCAN_BLOCKS) ? g_btot[t] : 0;
    int incl = warp_iscan(v, lane);
    if (lane == 31) wtot[w] = incl;
    __syncthreads();
    if (w == 0) {
        int wv = (lane < 8) ? wtot[lane] : 0;
        wv = warp_iscan(wv, lane);
        if (lane < 8) wtot[lane] = wv;
    }
    __syncthreads();
    int base = (w > 0) ? wtot[w - 1] : 0;
    if (t < SCAN_BLOCKS) g_boff[t] = base + incl - v;
    if (t == 255) g_rowptr[N_NODES] = wtot[7];
}

__global__ void scan_phase3_kernel() {
    int i = blockIdx.x * 256 + threadIdx.x;
    if (i >= N_NODES) return;
    g_rowptr[i] += g_boff[blockIdx.x];
    g_dinv[i] = rsqrtf((float)(g_indeg[i] + 1));
}

__global__ void scatter_kernel(const void* __restrict__ ei) {
    int e = blockIdx.x * blockDim.x + threadIdx.x;
    if (e >= N_EDGES) return;
    int is64 = g_is64;
    int s = load_idx(ei, e, is64);
    int d = load_idx(ei, (long long)N_EDGES + e, is64);
    if (s != d) {
        int pos = g_rowptr[d] + atomicAdd(&g_fill[d], 1);
        g_col[pos] = s;
    }
}

// ---------------- wmma tf32 GEMM: g_Hh = src @ W  (128x128 tile, BK=32) -------
// use_bn != 0: read fp32 xin (harness input), apply y = x*scale + shift inline.
// use_bn == 0: read device-global fp16 g_Xh (device-side symbol ONLY — the host
// must NEVER pass &g_Xh: on GB300 ATS that silently reads the host shadow).
__global__ __launch_bounds__(256) void gemm_wmma_kernel(const float* __restrict__ xin,
                                                        const float* __restrict__ W,
                                                        int use_bn) {
    const int m0 = blockIdx.x * 128;
    __shared__ __align__(16) float As[128][40];
    __shared__ __align__(16) float Bs[32][136];
    int tid = threadIdx.x;
    int wid = tid >> 5;
    int lane = tid & 31;
    int wm = wid >> 1;
    int wn = wid & 1;

    wmma::fragment<wmma::accumulator, 16, 16, 8, float> acc[2][4];
    #pragma unroll
    for (int i = 0; i < 2; i++)
        #pragma unroll
        for (int j = 0; j < 4; j++) wmma::fill_fragment(acc[i][j], 0.0f);

    for (int k0 = 0; k0 < 128; k0 += 32) {
        if (use_bn) {
            // fp32 input + BN fused
            #pragma unroll
            for (int t = 0; t < 4; t++) {
                int i = tid + t * 256;
                int r = i >> 3, c4 = i & 7;
                int gr = m0 + r;
                float4 v = (gr < N_NODES) ? ((const float4*)xin)[gr * 32 + (k0 >> 2) + c4]
                                          : make_float4(0.f, 0.f, 0.f, 0.f);
                if (gr < N_NODES) {
                    float4 scl = ((const float4*)g_bn_scale)[(k0 >> 2) + c4];
                    float4 sh  = ((const float4*)g_bn_shift)[(k0 >> 2) + c4];
                    v.x = fmaf(v.x, scl.x, sh.x);
                    v.y = fmaf(v.y, scl.y, sh.y);
                    v.z = fmaf(v.z, scl.z, sh.z);
                    v.w = fmaf(v.w, scl.w, sh.w);
                }
                As[r][c4 * 4 + 0] = f2tf32f(v.x);
                As[r][c4 * 4 + 1] = f2tf32f(v.y);
                As[r][c4 * 4 + 2] = f2tf32f(v.z);
                As[r][c4 * 4 + 3] = f2tf32f(v.w);
            }
        } else {
            // fp16 g_Xh input; fp16 -> fp32 is exact and already tf32-representable
            const uint4* __restrict__ a8 = (const uint4*)g_Xh;
            #pragma unroll
            for (int t = 0; t < 2; t++) {
                int i = tid + t * 256;
                int r = i >> 2, c8 = i & 3;
                int gr = m0 + r;
                uint4 u = (gr < N_NODES) ? a8[gr * 16 + (k0 >> 3) + c8]
                                         : make_uint4(0u, 0u, 0u, 0u);
                __half2* hp = (__half2*)&u;
                #pragma unroll
                for (int q = 0; q < 4; q++) {
                    float2 f2 = __half22float2(hp[q]);
                    As[r][c8 * 8 + q * 2 + 0] = f2.x;
                    As[r][c8 * 8 + q * 2 + 1] = f2.y;
                }
            }
        }
        #pragma unroll
        for (int t = 0; t < 4; t++) {
            int i = tid + t * 256;
            int r = i >> 5, c4 = i & 31;
            float4 v = ((const float4*)W)[(k0 + r) * 32 + c4];
            Bs[r][c4 * 4 + 0] = f2tf32f(v.x);
            Bs[r][c4 * 4 + 1] = f2tf32f(v.y);
            Bs[r][c4 * 4 + 2] = f2tf32f(v.z);
            Bs[r][c4 * 4 + 3] = f2tf32f(v.w);
        }
        __syncthreads();

        #pragma unroll
        for (int kk = 0; kk < 32; kk += 8) {
            wmma::fragment<wmma::matrix_a, 16, 16, 8, wmma::precision::tf32, wmma::row_major> af[2];
            wmma::fragment<wmma::matrix_b, 16, 16, 8, wmma::precision::tf32, wmma::row_major> bf[4];
            #pragma unroll
            for (int i = 0; i < 2; i++)
                wmma::load_matrix_sync(af[i], &As[wm * 32 + i * 16][kk], 40);
            #pragma unroll
            for (int j = 0; j < 4; j++)
                wmma::load_matrix_sync(bf[j], &Bs[kk][wn * 64 + j * 16], 136);
            #pragma unroll
            for (int i = 0; i < 2; i++)
                #pragma unroll
                for (int j = 0; j < 4; j++)
                    wmma::mma_sync(acc[i][j], af[i], bf[j], acc[i][j]);
        }
        __syncthreads();
    }

    // epilogue: stage each 16x16 fragment through smem, convert to fp16, store
    float* stage = &As[0][0] + wid * 320;     // 16 rows x ld 20 per warp
    #pragma unroll
    for (int i = 0; i < 2; i++) {
        int gr0 = m0 + wm * 32 + i * 16;
        if (gr0 + 16 <= N_NODES) {
            #pragma unroll
            for (int j = 0; j < 4; j++) {
                wmma::store_matrix_sync(stage, acc[i][j], 20, wmma::mem_row_major);
                __syncwarp();
                int r = lane >> 1, cc = (lane & 1) * 8;
                float4 v0 = *(float4*)&stage[r * 20 + cc];
                float4 v1 = *(float4*)&stage[r * 20 + cc + 4];
                __half2 h0 = __floats2half2_rn(v0.x, v0.y);
                __half2 h1 = __floats2half2_rn(v0.z, v0.w);
                __half2 h2 = __floats2half2_rn(v1.x, v1.y);
                __half2 h3 = __floats2half2_rn(v1.z, v1.w);
                uint4 u;
                u.x = *(uint32_t*)&h0; u.y = *(uint32_t*)&h1;
                u.z = *(uint32_t*)&h2; u.w = *(uint32_t*)&h3;
                *(uint4*)&g_Hh[(gr0 + r) * F + wn * 64 + j * 16 + cc] = u;
                __syncwarp();
            }
        }
    }
}

// ---------------- aggregate + bias + squash + attention -----------------------
// fp16 gather; edge cols + dinv batched 32-at-a-time via shuffles so the only
// per-edge memory op is the H-row load (deep MLP, chain depth 1).
__global__ __launch_bounds__(256) void agg_squash_kernel(const float* __restrict__ bias,
                                                         const float* __restrict__ watt) {
    int gtid = blockIdx.x * blockDim.x + threadIdx.x;
    int n = gtid >> 5;
    if (n >= N_NODES) return;
    int l = threadIdx.x & 31;

    const uint2* __restrict__ H2 = (const uint2*)g_Hh;
    float di = g_dinv[n];
    float w = di * di;                       // self loop weight

    uint2 su = H2[n * 32 + l];
    __half2* sp = (__half2*)&su;
    float2 s0f = __half22float2(sp[0]);
    float2 s1f = __half22float2(sp[1]);
    float4 acc = make_float4(w * s0f.x, w * s0f.y, w * s1f.x, w * s1f.y);

    int beg = g_rowptr[n];
    int cnt = g_rowptr[n + 1] - beg;

    for (int base = 0; base < cnt; base += 32) {
        int m = cnt - base; if (m > 32) m = 32;
        int idx = 0; float dv = 0.0f;
        if (l < m) { idx = g_col[beg + base + l]; dv = g_dinv[idx]; }
        int j = 0;
        for (; j + 1 < m; j += 2) {
            int n0 = __shfl_sync(0xffffffffu, idx, j);
            int n1 = __shfl_sync(0xffffffffu, idx, j + 1);
            float w0 = di * __shfl_sync(0xffffffffu, dv, j);
            float w1 = di * __shfl_sync(0xffffffffu, dv, j + 1);
            uint2 u0 = H2[n0 * 32 + l];
            uint2 u1 = H2[n1 * 32 + l];
            __half2* p0 = (__half2*)&u0;
            __half2* p1 = (__half2*)&u1;
            float2 a0 = __half22float2(p0[0]), a1 = __half22float2(p0[1]);
            float2 b0 = __half22float2(p1[0]), b1 = __half22float2(p1[1]);
            acc.x = fmaf(w0, a0.x, acc.x); acc.x = fmaf(w1, b0.x, acc.x);
            acc.y = fmaf(w0, a0.y, acc.y); acc.y = fmaf(w1, b0.y, acc.y);
            acc.z = fmaf(w0, a1.x, acc.z); acc.z = fmaf(w1, b1.x, acc.z);
            acc.w = fmaf(w0, a1.y, acc.w); acc.w = fmaf(w1, b1.y, acc.w);
        }
        if (j < m) {
            int n0 = __shfl_sync(0xffffffffu, idx, j);
            float w0 = di * __shfl_sync(0xffffffffu, dv, j);
            uint2 u0 = H2[n0 * 32 + l];
            __half2* p0 = (__half2*)&u0;
            float2 a0 = __half22float2(p0[0]), a1 = __half22float2(p0[1]);
            acc.x = fmaf(w0, a0.x, acc.x);
            acc.y = fmaf(w0, a0.y, acc.y);
            acc.z = fmaf(w0, a1.x, acc.z);
            acc.w = fmaf(w0, a1.y, acc.w);
        }
    }
    float4 b4 = ((const float4*)bias)[l];
    acc.x += b4.x; acc.y += b4.y; acc.z += b4.z; acc.w += b4.w;

    float n2p = acc.x * acc.x + acc.y * acc.y + acc.z * acc.z + acc.w * acc.w;
    float n2 = warp_sum(n2p);
    float scl = (n2 / (1.0f + n2)) * rsqrtf(n2 + 1e-8f);
    float4 out = make_float4(scl * acc.x, scl * acc.y, scl * acc.z, scl * acc.w);

    // store X as fp16 (tf32-equivalent mantissa; next GEMM rounds to tf32 anyway)
    __half2 o0 = __floats2half2_rn(out.x, out.y);
    __half2 o1 = __floats2half2_rn(out.z, out.w);
    uint2 st; st.x = *(uint32_t*)&o0; st.y = *(uint32_t*)&o1;
    ((uint2*)g_Xh)[n * 32 + l] = st;

    // attention from full-precision out
    float4 w4 = ((const float4*)watt)[l];
    float ap = out.x * w4.x + out.y * w4.y + out.z * w4.z + out.w * w4.w;
    float a = warp_sum(ap);
    if (l == 0) g_att[n] = a;
}

// ---------------- per-graph readout (sorted batch; 4-way node split) ----------
__global__ __launch_bounds__(512) void readout_kernel(const void* __restrict__ batch) {
    __shared__ float sws[4][F], ssm[4][F], smx[4][F];
    int g = blockIdx.x;
    int tid = threadIdx.x;
    int f = tid & 127;
    int part = tid >> 7;          // 0..3
    int is64 = g_is64;

    int lo = 0, hi = N_NODES;
    while (lo < hi) { int mid = (lo + hi) >> 1; if (load_idx(batch, mid, is64) < g) lo = mid + 1; else hi = mid; }
    int start = lo;
    lo = start; hi = N_NODES;
    while (lo < hi) { int mid = (lo + hi) >> 1; if (load_idx(batch, mid, is64) < g + 1) lo = mid + 1; else hi = mid; }
    int end = lo;

    float ws = 0.0f, sm = 0.0f, mx = -INFINITY;
    for (int n = start + part; n < end; n += 4) {
        float v = __half2float(g_Xh[n * F + f]);
        float a = g_att[n];
        ws = fmaf(a, v, ws);
        sm += v;
        mx = fmaxf(mx, v);
    }
    sws[part][f] = ws; ssm[part][f] = sm; smx[part][f] = mx;
    __syncthreads();
    if (part == 0) {
        #pragma unroll
        for (int p = 1; p < 4; p++) {
            ws += sws[p][f];
            sm += ssm[p][f];
            mx = fmaxf(mx, smx[p][f]);
        }
        float cnt = fmaxf((float)(end - start), 1.0f);
        g_rep[g * 3 * F + f]         += ws;
        g_rep[g * 3 * F + F + f]     += sm / cnt;
        g_rep[g * 3 * F + 2 * F + f] += (start < end) ? mx : 0.0f;
    }
}

// ---------------- final MLP + log_softmax ----------------
__global__ void mlp_kernel(const float* __restrict__ W1, const float* __restrict__ b1,
                           const float* __restrict__ W2, const float* __restrict__ b2,
                           float* __restrict__ out) {
    __shared__ float h[F];
    __shared__ float lg[NC];
    int g = blockIdx.x;
    int j = threadIdx.x;

    float acc = b1[j];
    const float* rep = &g_rep[g * 3 * F];
    for (int k = 0; k < 3 * F; k++)
        acc = fmaf(rep[k], W1[k * F + j], acc);
    h[j] = fmaxf(acc, 0.0f);
    __syncthreads();

    if (j < NC) {
        float l = b2[j];
        for (int k = 0; k < F; k++) l = fmaf(h[k], W2[k * NC + j], l);
        lg[j] = l;
    }
    __syncthreads();
    if (j < NC) {
        float m = -INFINITY;
        #pragma unroll
        for (int c = 0; c < NC; c++) m = fmaxf(m, lg[c]);
        float s = 0.0f;
        #pragma unroll
        for (int c = 0; c < NC; c++) s += expf(lg[c] - m);
        out[g * NC + j] = lg[j] - m - logf(s);
    }
}

// ---------------- launcher ----------------
extern "C" void kernel_launch(void* const* d_in, const int* in_sizes, int n_in,
                              void* d_out, int out_size) {
    const float* x      = (const float*)d_in[0];
    const void*  ei     = d_in[1];
    const void*  batch  = d_in[2];
    const float* gamma  = (const float*)d_in[3];
    const float* beta   = (const float*)d_in[4];
    const float* gcn_w  = (const float*)d_in[5];
    const float* gcn_b  = (const float*)d_in[6];
    const float* w_att  = (const float*)d_in[7];
    const float* lin1_w = (const float*)d_in[8];
    const float* lin1_b = (const float*)d_in[9];
    const float* lin2_w = (const float*)d_in[10];
    const float* lin2_b = (const float*)d_in[11];
    float* out = (float*)d_out;

    static cudaStream_t s1 = nullptr;
    static cudaEvent_t evFork, evStruct, evA0, evR0, evA1, evR1;
    if (!s1) {
        cudaStreamCreateWithFlags(&s1, cudaStreamNonBlocking);
        cudaEventCreateWithFlags(&evFork,   cudaEventDisableTiming);
        cudaEventCreateWithFlags(&evStruct, cudaEventDisableTiming);
        cudaEventCreateWithFlags(&evA0,     cudaEventDisableTiming);
        cudaEventCreateWithFlags(&evR0,     cudaEventDisableTiming);
        cudaEventCreateWithFlags(&evA1,     cudaEventDisableTiming);
        cudaEventCreateWithFlags(&evR1,     cudaEventDisableTiming);
    }
    cudaStream_t s0 = 0;

    // fork: init (zero + detect) + structure build on s1; BN chain starts on s0
    cudaEventRecord(evFork, s0);
    cudaStreamWaitEvent(s1, evFork, 0);
    init_rest_kernel<<<256, 256, 0, s1>>>(ei);
    deg_count_kernel<<<(N_EDGES + 255) / 256, 256, 0, s1>>>(ei);
    scan_phase1_kernel<<<SCAN_BLOCKS, 256, 0, s1>>>();
    scan_phase2_kernel<<<1, 256, 0, s1>>>();
    scan_phase3_kernel<<<SCAN_BLOCKS, 256, 0, s1>>>();
    scatter_kernel<<<(N_EDGES + 255) / 256, 256, 0, s1>>>(ei);
    cudaEventRecord(evStruct, s1);

    zero_stats_kernel<<<1, 256, 0, s0>>>();
    bn_stats_kernel<<<(N_NODES + 63) / 64, 128, 0, s0>>>(x);
    bn_prep_kernel<<<1, F, 0, s0>>>(gamma, beta);

    int gemm_grid = (N_NODES + 127) / 128;
    int agg_blocks = (N_NODES * 32 + 255) / 256;

    // layer 0 (BN fused into A-load; kernel reads g_Xh internally when use_bn=0)
    gemm_wmma_kernel<<<gemm_grid, 256, 0, s0>>>(x, gcn_w + 0 * F * F, 1);
    cudaStreamWaitEvent(s0, evStruct, 0);
    agg_squash_kernel<<<agg_blocks, 256, 0, s0>>>(gcn_b + 0 * F, w_att + 0 * F);
    cudaEventRecord(evA0, s0);
    cudaStreamWaitEvent(s1, evA0, 0);
    readout_kernel<<<NG, 512, 0, s1>>>(batch);    // overlaps gemm1
    cudaEventRecord(evR0, s1);

    // layer 1
    gemm_wmma_kernel<<<gemm_grid, 256, 0, s0>>>(x, gcn_w + 1 * F * F, 0);
    cudaStreamWaitEvent(s0, evR0, 0);
    agg_squash_kernel<<<agg_blocks, 256, 0, s0>>>(gcn_b + 1 * F, w_att + 1 * F);
    cudaEventRecord(evA1, s0);
    cudaStreamWaitEvent(s1, evA1, 0);
    readout_kernel<<<NG, 512, 0, s1>>>(batch);    // overlaps gemm2
    cudaEventRecord(evR1, s1);

    // layer 2
    gemm_wmma_kernel<<<gemm_grid, 256, 0, s0>>>(x, gcn_w + 2 * F * F, 0);
    cudaStreamWaitEvent(s0, evR1, 0);
    agg_squash_kernel<<<agg_blocks, 256, 0, s0>>>(gcn_b + 2 * F, w_att + 2 * F);
    readout_kernel<<<NG, 512, 0, s0>>>(batch);

    mlp_kernel<<<NG, F, 0, s0>>>(lin1_w, lin1_b, lin2_w, lin2_b, out);
}

// round 15
// speedup vs baseline: 2.5671x; 1.3289x over previous
#include <cuda_runtime.h>
#include <cuda_fp16.h>
#include <mma.h>
#include <math.h>
#include <stdint.h>

using namespace nvcuda;

#define N_NODES 50000
#define N_EDGES 640000
#define F 128
#define NG 256
#define NC 10
#define NL 3
#define SCAN_BLOCKS 196   // 196 * 256 = 50176 >= 50000; all co-resident (no smem)

// ---------------- device scratch (no allocations allowed) ----------------
__device__ __half g_Xh[N_NODES * F];     // current node features (fp16 = tf32 mantissa)
__device__ __half g_Hh[N_NODES * F];     // post-GEMM features (fp16)
__device__ float  g_att[N_NODES];
__device__ float  g_dinv[N_NODES];
__device__ int    g_indeg[N_NODES];      // zeroed by previous call's tail (or BSS init)
__device__ int    g_rowptr[N_NODES + 1];
__device__ int    g_fill[N_NODES];       // zeroed by tail
__device__ int    g_col[N_EDGES];
__device__ int    g_btot[SCAN_BLOCKS];
__device__ int    g_boff[SCAN_BLOCKS];
__device__ int    g_scan_ct;             // zeroed by tail
__device__ int    g_scan_ready;          // zeroed by tail
__device__ float  g_stats[2 * F];        // zeroed by tail
__device__ float  g_rep[NG * 3 * F];     // zeroed by tail
__device__ int    g_is64;

// ---------------- helpers ----------------
__device__ __forceinline__ float warp_sum(float v) {
    #pragma unroll
    for (int o = 16; o; o >>= 1) v += __shfl_xor_sync(0xffffffffu, v, o);
    return v;
}
__device__ __forceinline__ int load_idx(const void* p, long long i, int is64) {
    if (is64) return (int)((const long long*)p)[i];
    return ((const int*)p)[i];
}
__device__ __forceinline__ int warp_iscan(int v, int lane) {
    #pragma unroll
    for (int o = 1; o < 32; o <<= 1) {
        int t = __shfl_up_sync(0xffffffffu, v, o);
        if (lane >= o) v += t;
    }
    return v;
}

// ---------------- dtype detection ----------------
__global__ void detect_kernel(const void* ei) {
    if (threadIdx.x == 0) {
        const long long* p = (const long long*)ei;
        int ok64 = 1;
        for (int k = 0; k < 32; k++) {
            long long a = p[k];
            long long b = p[N_EDGES + k];
            if (a < 0 || a >= N_NODES || b < 0 || b >= N_NODES) { ok64 = 0; break; }
        }
        g_is64 = ok64;
    }
}

// ---------------- graph structure ----------------
__global__ void deg_count_kernel(const void* __restrict__ ei) {
    int e = blockIdx.x * blockDim.x + threadIdx.x;
    if (e >= N_EDGES) return;
    int is64 = g_is64;
    int s = load_idx(ei, e, is64);
    int d = load_idx(ei, (long long)N_EDGES + e, is64);
    if (s != d) atomicAdd(&g_indeg[d], 1);
}

// single-kernel exclusive scan: block-local scan -> ticket -> last block scans
// the 196 block totals -> all blocks apply offsets. All 196 blocks co-resident.
__global__ void scan_fused_kernel() {
    __shared__ int wtot[8];
    __shared__ int s_last;
    int t = threadIdx.x, lane = t & 31, w = t >> 5;
    int b = blockIdx.x;
    int i = b * 256 + t;
    int v = (i < N_NODES) ? g_indeg[i] : 0;
    int incl = warp_iscan(v, lane);
    if (lane == 31) wtot[w] = incl;
    __syncthreads();
    if (w == 0) {
        int wv = (lane < 8) ? wtot[lane] : 0;
        wv = warp_iscan(wv, lane);
        if (lane < 8) wtot[lane] = wv;
    }
    __syncthreads();
    int base = (w > 0) ? wtot[w - 1] : 0;
    int local_excl = base + incl - v;
    if (i < N_NODES) g_rowptr[i] = local_excl;

    if (t == 255) {
        g_btot[b] = base + incl;
        __threadfence();
        int old = atomicAdd(&g_scan_ct, 1);
        s_last = (old == SCAN_BLOCKS - 1);
    }
    __syncthreads();

    if (s_last) {
        // this block cooperatively scans the 196 block totals
        __syncthreads();   // reuse wtot safely
        int bv = (t < SCAN_BLOCKS) ? g_btot[t] : 0;
        int bincl = warp_iscan(bv, lane);
        if (lane == 31) wtot[w] = bincl;
        __syncthreads();
        if (w == 0) {
            int wv = (lane < 8) ? wtot[lane] : 0;
            wv = warp_iscan(wv, lane);
            if (lane < 8) wtot[lane] = wv;
        }
        __syncthreads();
        int bbase = (w > 0) ? wtot[w - 1] : 0;
        if (t < SCAN_BLOCKS) g_boff[t] = bbase + bincl - bv;
        if (t == 255) g_rowptr[N_NODES] = wtot[7];
        __threadfence();
        if (t == 0) atomicExch(&g_scan_ready, 1);
    } else {
        if (t == 0) {
            while (atomicAdd(&g_scan_ready, 0) == 0) { __nanosleep(100); }
        }
        __syncthreads();
        __threadfence();
    }

    int off = g_boff[b];
    if (i < N_NODES) {
        g_rowptr[i] = local_excl + off;
        g_dinv[i] = rsqrtf((float)(g_indeg[i] + 1));
    }
}

__global__ void scatter_kernel(const void* __restrict__ ei) {
    int e = blockIdx.x * blockDim.x + threadIdx.x;
    if (e >= N_EDGES) return;
    int is64 = g_is64;
    int s = load_idx(ei, e, is64);
    int d = load_idx(ei, (long long)N_EDGES + e, is64);
    if (s != d) {
        int pos = g_rowptr[d] + atomicAdd(&g_fill[d], 1);
        g_col[pos] = s;
    }
}

// ---------------- batchnorm stats (g_stats pre-zeroed by tail) ----------------
__global__ void bn_stats_kernel(const float* __restrict__ x) {
    int f = threadIdx.x;
    int r0 = blockIdx.x * 64;
    int r1 = min(r0 + 64, N_NODES);
    float s = 0.0f, s2 = 0.0f;
    for (int r = r0; r < r1; r++) {
        float v = x[r * F + f];
        s += v; s2 = fmaf(v, v, s2);
    }
    atomicAdd(&g_stats[f], s);
    atomicAdd(&g_stats[F + f], s2);
}

// ---------------- fp16 HMMA GEMM: g_Hh = src @ W  (128x128x128 full-K smem) ---
// use_bn != 0: read fp32 xin, compute BN scale/shift per-block from g_stats.
// use_bn == 0: read device-global fp16 g_Xh (device-side symbol ONLY — host must
// NEVER pass &g_Xh: GB300 ATS silently reads the host shadow).
#define GEMM_H_SMEM (2 * 128 * 136 * 2)   // As + Bs, half
__global__ __launch_bounds__(256) void gemm_h_kernel(const float* __restrict__ xin,
                                                     const float* __restrict__ W,
                                                     const float* __restrict__ gamma,
                                                     const float* __restrict__ beta,
                                                     int use_bn) {
    extern __shared__ __align__(16) __half smh[];
    __half* As = smh;                    // [128][136]
    __half* Bs = smh + 128 * 136;        // [128][136]
    __shared__ float s_scale[F], s_shift[F];

    const int m0 = blockIdx.x * 128;
    int tid = threadIdx.x;
    int wid = tid >> 5;
    int lane = tid & 31;
    int wm = wid >> 1;          // 0..3: 32-row slice
    int wn = wid & 1;           // 0..1: 64-col slice

    if (use_bn) {
        if (tid < F) {
            float inv_n = 1.0f / (float)N_NODES;
            float mu = g_stats[tid] * inv_n;
            float var = g_stats[F + tid] * inv_n - mu * mu;
            float rstd = rsqrtf(var + 1e-5f);
            float s = gamma[tid] * rstd;
            s_scale[tid] = s;
            s_shift[tid] = beta[tid] - mu * s;
        }
        __syncthreads();
    }

    // load A
    if (use_bn) {
        #pragma unroll
        for (int t = 0; t < 16; t++) {
            int i = tid + t * 256;               // 4096 float4 covers 128x128 f32
            int r = i >> 5, c4 = i & 31;
            int gr = m0 + r;
            float4 v = (gr < N_NODES) ? ((const float4*)xin)[gr * 32 + c4]
                                      : make_float4(0.f, 0.f, 0.f, 0.f);
            if (gr < N_NODES) {
                v.x = fmaf(v.x, s_scale[c4 * 4 + 0], s_shift[c4 * 4 + 0]);
                v.y = fmaf(v.y, s_scale[c4 * 4 + 1], s_shift[c4 * 4 + 1]);
                v.z = fmaf(v.z, s_scale[c4 * 4 + 2], s_shift[c4 * 4 + 2]);
                v.w = fmaf(v.w, s_scale[c4 * 4 + 3], s_shift[c4 * 4 + 3]);
            }
            __half2 h0 = __floats2half2_rn(v.x, v.y);
            __half2 h1 = __floats2half2_rn(v.z, v.w);
            uint2 u; u.x = *(uint32_t*)&h0; u.y = *(uint32_t*)&h1;
            *(uint2*)&As[r * 136 + c4 * 4] = u;
        }
    } else {
        const uint4* __restrict__ a8 = (const uint4*)g_Xh;
        #pragma unroll
        for (int t = 0; t < 8; t++) {
            int i = tid + t * 256;               // 2048 uint4 covers 128x128 half
            int r = i >> 4, c16 = i & 15;        // 8 halves per uint4
            int gr = m0 + r;
            uint4 u = (gr < N_NODES) ? a8[gr * 16 + c16] : make_uint4(0u, 0u, 0u, 0u);
            *(uint4*)&As[r * 136 + c16 * 8] = u;
        }
    }
    // load B (fp32 -> half)
    #pragma unroll
    for (int t = 0; t < 16; t++) {
        int i = tid + t * 256;                   // 4096 float4 covers 128x128 f32
        int r = i >> 5, c4 = i & 31;
        float4 v = ((const float4*)W)[r * 32 + c4];
        __half2 h0 = __floats2half2_rn(v.x, v.y);
        __half2 h1 = __floats2half2_rn(v.z, v.w);
        uint2 u; u.x = *(uint32_t*)&h0; u.y = *(uint32_t*)&h1;
        *(uint2*)&Bs[r * 136 + c4 * 4] = u;
    }
    __syncthreads();

    wmma::fragment<wmma::accumulator, 16, 16, 16, float> acc[2][4];
    #pragma unroll
    for (int i = 0; i < 2; i++)
        #pragma unroll
        for (int j = 0; j < 4; j++) wmma::fill_fragment(acc[i][j], 0.0f);

    #pragma unroll
    for (int k = 0; k < 8; k++) {
        wmma::fragment<wmma::matrix_a, 16, 16, 16, __half, wmma::row_major> af[2];
        wmma::fragment<wmma::matrix_b, 16, 16, 16, __half, wmma::row_major> bf[4];
        #pragma unroll
        for (int i = 0; i < 2; i++)
            wmma::load_matrix_sync(af[i], &As[(wm * 32 + i * 16) * 136 + k * 16], 136);
        #pragma unroll
        for (int j = 0; j < 4; j++)
            wmma::load_matrix_sync(bf[j], &Bs[(k * 16) * 136 + wn * 64 + j * 16], 136);
        #pragma unroll
        for (int i = 0; i < 2; i++)
            #pragma unroll
            for (int j = 0; j < 4; j++)
                wmma::mma_sync(acc[i][j], af[i], bf[j], acc[i][j]);
    }
    __syncthreads();   // before reusing smem as epilogue stage

    float* stage = ((float*)smh) + wid * 320;   // 16 rows x ld 20 per warp
    #pragma unroll
    for (int i = 0; i < 2; i++) {
        int gr0 = m0 + wm * 32 + i * 16;
        if (gr0 + 16 <= N_NODES) {
            #pragma unroll
            for (int j = 0; j < 4; j++) {
                wmma::store_matrix_sync(stage, acc[i][j], 20, wmma::mem_row_major);
                __syncwarp();
                int r = lane >> 1, cc = (lane & 1) * 8;
                float4 v0 = *(float4*)&stage[r * 20 + cc];
                float4 v1 = *(float4*)&stage[r * 20 + cc + 4];
                __half2 h0 = __floats2half2_rn(v0.x, v0.y);
                __half2 h1 = __floats2half2_rn(v0.z, v0.w);
                __half2 h2 = __floats2half2_rn(v1.x, v1.y);
                __half2 h3 = __floats2half2_rn(v1.z, v1.w);
                uint4 u;
                u.x = *(uint32_t*)&h0; u.y = *(uint32_t*)&h1;
                u.z = *(uint32_t*)&h2; u.w = *(uint32_t*)&h3;
                *(uint4*)&g_Hh[(gr0 + r) * F + wn * 64 + j * 16 + cc] = u;
                __syncwarp();
            }
        }
    }
}

// ---------------- aggregate + bias + squash + attention (unchanged from R14) --
__global__ __launch_bounds__(256) void agg_squash_kernel(const float* __restrict__ bias,
                                                         const float* __restrict__ watt) {
    int gtid = blockIdx.x * blockDim.x + threadIdx.x;
    int n = gtid >> 5;
    if (n >= N_NODES) return;
    int l = threadIdx.x & 31;

    const uint2* __restrict__ H2 = (const uint2*)g_Hh;
    float di = g_dinv[n];
    float w = di * di;

    uint2 su = H2[n * 32 + l];
    __half2* sp = (__half2*)&su;
    float2 s0f = __half22float2(sp[0]);
    float2 s1f = __half22float2(sp[1]);
    float4 acc = make_float4(w * s0f.x, w * s0f.y, w * s1f.x, w * s1f.y);

    int beg = g_rowptr[n];
    int cnt = g_rowptr[n + 1] - beg;

    for (int base = 0; base < cnt; base += 32) {
        int m = cnt - base; if (m > 32) m = 32;
        int idx = 0; float dv = 0.0f;
        if (l < m) { idx = g_col[beg + base + l]; dv = g_dinv[idx]; }
        int j = 0;
        for (; j + 1 < m; j += 2) {
            int n0 = __shfl_sync(0xffffffffu, idx, j);
            int n1 = __shfl_sync(0xffffffffu, idx, j + 1);
            float w0 = di * __shfl_sync(0xffffffffu, dv, j);
            float w1 = di * __shfl_sync(0xffffffffu, dv, j + 1);
            uint2 u0 = H2[n0 * 32 + l];
            uint2 u1 = H2[n1 * 32 + l];
            __half2* p0 = (__half2*)&u0;
            __half2* p1 = (__half2*)&u1;
            float2 a0 = __half22float2(p0[0]), a1 = __half22float2(p0[1]);
            float2 b0 = __half22float2(p1[0]), b1 = __half22float2(p1[1]);
            acc.x = fmaf(w0, a0.x, acc.x); acc.x = fmaf(w1, b0.x, acc.x);
            acc.y = fmaf(w0, a0.y, acc.y); acc.y = fmaf(w1, b0.y, acc.y);
            acc.z = fmaf(w0, a1.x, acc.z); acc.z = fmaf(w1, b1.x, acc.z);
            acc.w = fmaf(w0, a1.y, acc.w); acc.w = fmaf(w1, b1.y, acc.w);
        }
        if (j < m) {
            int n0 = __shfl_sync(0xffffffffu, idx, j);
            float w0 = di * __shfl_sync(0xffffffffu, dv, j);
            uint2 u0 = H2[n0 * 32 + l];
            __half2* p0 = (__half2*)&u0;
            float2 a0 = __half22float2(p0[0]), a1 = __half22float2(p0[1]);
            acc.x = fmaf(w0, a0.x, acc.x);
            acc.y = fmaf(w0, a0.y, acc.y);
            acc.z = fmaf(w0, a1.x, acc.z);
            acc.w = fmaf(w0, a1.y, acc.w);
        }
    }
    float4 b4 = ((const float4*)bias)[l];
    acc.x += b4.x; acc.y += b4.y; acc.z += b4.z; acc.w += b4.w;

    float n2p = acc.x * acc.x + acc.y * acc.y + acc.z * acc.z + acc.w * acc.w;
    float n2 = warp_sum(n2p);
    float scl = (n2 / (1.0f + n2)) * rsqrtf(n2 + 1e-8f);
    float4 out = make_float4(scl * acc.x, scl * acc.y, scl * acc.z, scl * acc.w);

    __half2 o0 = __floats2half2_rn(out.x, out.y);
    __half2 o1 = __floats2half2_rn(out.z, out.w);
    uint2 st; st.x = *(uint32_t*)&o0; st.y = *(uint32_t*)&o1;
    ((uint2*)g_Xh)[n * 32 + l] = st;

    float4 w4 = ((const float4*)watt)[l];
    float ap = out.x * w4.x + out.y * w4.y + out.z * w4.z + out.w * w4.w;
    float a = warp_sum(ap);
    if (l == 0) g_att[n] = a;
}

// ---------------- per-graph readout (sorted batch; 4-way node split) ----------
__global__ __launch_bounds__(512) void readout_kernel(const void* __restrict__ batch) {
    __shared__ float sws[4][F], ssm[4][F], smx[4][F];
    int g = blockIdx.x;
    int tid = threadIdx.x;
    int f = tid & 127;
    int part = tid >> 7;
    int is64 = g_is64;

    int lo = 0, hi = N_NODES;
    while (lo < hi) { int mid = (lo + hi) >> 1; if (load_idx(batch, mid, is64) < g) lo = mid + 1; else hi = mid; }
    int start = lo;
    lo = start; hi = N_NODES;
    while (lo < hi) { int mid = (lo + hi) >> 1; if (load_idx(batch, mid, is64) < g + 1) lo = mid + 1; else hi = mid; }
    int end = lo;

    float ws = 0.0f, sm = 0.0f, mx = -INFINITY;
    for (int n = start + part; n < end; n += 4) {
        float v = __half2float(g_Xh[n * F + f]);
        float a = g_att[n];
        ws = fmaf(a, v, ws);
        sm += v;
        mx = fmaxf(mx, v);
    }
    sws[part][f] = ws; ssm[part][f] = sm; smx[part][f] = mx;
    __syncthreads();
    if (part == 0) {
        #pragma unroll
        for (int p = 1; p < 4; p++) {
            ws += sws[p][f];
            sm += ssm[p][f];
            mx = fmaxf(mx, smx[p][f]);
        }
        float cnt = fmaxf((float)(end - start), 1.0f);
        g_rep[g * 3 * F + f]         += ws;
        g_rep[g * 3 * F + F + f]     += sm / cnt;
        g_rep[g * 3 * F + 2 * F + f] += (start < end) ? mx : 0.0f;
    }
}

// ---------------- final MLP + log_softmax + tail scratch zeroing --------------
__global__ void mlp_kernel(const float* __restrict__ W1, const float* __restrict__ b1,
                           const float* __restrict__ W2, const float* __restrict__ b2,
                           float* __restrict__ out) {
    __shared__ float h[F];
    __shared__ float lg[NC];
    int g = blockIdx.x;
    int j = threadIdx.x;

    float acc = b1[j];
    float* rep = &g_rep[g * 3 * F];
    for (int k = 0; k < 3 * F; k++)
        acc = fmaf(rep[k], W1[k * F + j], acc);
    h[j] = fmaxf(acc, 0.0f);
    __syncthreads();                    // all rep reads done

    // zero this graph's rep region for the next invocation
    #pragma unroll
    for (int k = 0; k < 3; k++) rep[k * F + j] = 0.0f;

    if (j < NC) {
        float l = b2[j];
        for (int k = 0; k < F; k++) l = fmaf(h[k], W2[k * NC + j], l);
        lg[j] = l;
    }
    __syncthreads();
    if (j < NC) {
        float m = -INFINITY;
        #pragma unroll
        for (int c = 0; c < NC; c++) m = fmaxf(m, lg[c]);
        float s = 0.0f;
        #pragma unroll
        for (int c = 0; c < NC; c++) s += expf(lg[c] - m);
        out[g * NC + j] = lg[j] - m - logf(s);
    }

    // grid-stride tail zeroing of per-call scratch
    int gid = blockIdx.x * blockDim.x + threadIdx.x;
    int gstride = gridDim.x * blockDim.x;          // 256*128 = 32768
    for (int i = gid; i < N_NODES; i += gstride) { g_indeg[i] = 0; g_fill[i] = 0; }
    if (gid < 2 * F) g_stats[gid] = 0.0f;
    if (gid == 0) { g_scan_ct = 0; g_scan_ready = 0; }
}

// ---------------- launcher ----------------
extern "C" void kernel_launch(void* const* d_in, const int* in_sizes, int n_in,
                              void* d_out, int out_size) {
    const float* x      = (const float*)d_in[0];
    const void*  ei     = d_in[1];
    const void*  batch  = d_in[2];
    const float* gamma  = (const float*)d_in[3];
    const float* beta   = (const float*)d_in[4];
    const float* gcn_w  = (const float*)d_in[5];
    const float* gcn_b  = (const float*)d_in[6];
    const float* w_att  = (const float*)d_in[7];
    const float* lin1_w = (const float*)d_in[8];
    const float* lin1_b = (const float*)d_in[9];
    const float* lin2_w = (const float*)d_in[10];
    const float* lin2_b = (const float*)d_in[11];
    float* out = (float*)d_out;

    static cudaStream_t s1 = nullptr;
    static cudaEvent_t evFork, evStruct, evA0, evR0, evA1, evR1;
    if (!s1) {
        cudaStreamCreateWithFlags(&s1, cudaStreamNonBlocking);
        cudaEventCreateWithFlags(&evFork,   cudaEventDisableTiming);
        cudaEventCreateWithFlags(&evStruct, cudaEventDisableTiming);
        cudaEventCreateWithFlags(&evA0,     cudaEventDisableTiming);
        cudaEventCreateWithFlags(&evR0,     cudaEventDisableTiming);
        cudaEventCreateWithFlags(&evA1,     cudaEventDisableTiming);
        cudaEventCreateWithFlags(&evR1,     cudaEventDisableTiming);
        cudaFuncSetAttribute(gemm_h_kernel, cudaFuncAttributeMaxDynamicSharedMemorySize,
                             GEMM_H_SMEM);
    }
    cudaStream_t s0 = 0;

    // s1: structure chain (launch indices 0-3 so ncu -s 5 lands on gemm0)
    cudaEventRecord(evFork, s0);
    cudaStreamWaitEvent(s1, evFork, 0);
    detect_kernel<<<1, 32, 0, s1>>>(ei);                               // 0
    deg_count_kernel<<<(N_EDGES + 255) / 256, 256, 0, s1>>>(ei);       // 1
    scan_fused_kernel<<<SCAN_BLOCKS, 256, 0, s1>>>();                  // 2
    scatter_kernel<<<(N_EDGES + 255) / 256, 256, 0, s1>>>(ei);         // 3
    cudaEventRecord(evStruct, s1);

    // s0: BN stats
    bn_stats_kernel<<<(N_NODES + 63) / 64, 128, 0, s0>>>(x);           // 4

    int gemm_grid = (N_NODES + 127) / 128;
    int agg_blocks = (N_NODES * 32 + 255) / 256;

    // layer 0 (BN prep+apply fused into GEMM A-load)
    gemm_h_kernel<<<gemm_grid, 256, GEMM_H_SMEM, s0>>>(x, gcn_w + 0 * F * F, gamma, beta, 1);  // 5
    cudaStreamWaitEvent(s0, evStruct, 0);
    agg_squash_kernel<<<agg_blocks, 256, 0, s0>>>(gcn_b + 0 * F, w_att + 0 * F);               // 6
    cudaEventRecord(evA0, s0);
    cudaStreamWaitEvent(s1, evA0, 0);
    readout_kernel<<<NG, 512, 0, s1>>>(batch);                                                 // 7
    cudaEventRecord(evR0, s1);

    // layer 1
    gemm_h_kernel<<<gemm_grid, 256, GEMM_H_SMEM, s0>>>(x, gcn_w + 1 * F * F, gamma, beta, 0);  // 8
    cudaStreamWaitEvent(s0, evR0, 0);
    agg_squash_kernel<<<agg_blocks, 256, 0, s0>>>(gcn_b + 1 * F, w_att + 1 * F);               // 9
    cudaEventRecord(evA1, s0);
    cudaStreamWaitEvent(s1, evA1, 0);
    readout_kernel<<<NG, 512, 0, s1>>>(batch);                                                 // 10
    cudaEventRecord(evR1, s1);

    // layer 2
    gemm_h_kernel<<<gemm_grid, 256, GEMM_H_SMEM, s0>>>(x, gcn_w + 2 * F * F, gamma, beta, 0);  // 11
    cudaStreamWaitEvent(s0, evR1, 0);
    agg_squash_kernel<<<agg_blocks, 256, 0, s0>>>(gcn_b + 2 * F, w_att + 2 * F);               // 12
    readout_kernel<<<NG, 512, 0, s0>>>(batch);                                                 // 13
    mlp_kernel<<<NG, F, 0, s0>>>(lin1_w, lin1_b, lin2_w, lin2_b, out);                         // 14
}